// round 5
// baseline (speedup 1.0000x reference)
#include <cuda_runtime.h>

// Problem dims (fixed for this problem instance)
#define NR   8192   // rows (nodes)
#define DIN  512    // input feature dim
#define DOUT 128    // output feature dim

// ---------------- scratch (static device globals; no allocation) ----------------
__device__ __align__(16) float g_hw1[DOUT * DIN];   // proj(expmap0(lin_weight))
__device__ __align__(16) float g_hw2[DOUT * DOUT];  // proj(expmap0(agg_weight))
__device__ __align__(16) float g_hb[DOUT];          // proj(expmap0(lin_bias))
__device__ float g_hb2s;                            // sum hb^2
__device__ float g_b2s;                             // sum agg_bias^2
__device__ float g_xn[NR];                          // ||x_i|| (clamped)
__device__ __align__(16) float g_h[NR * DOUT];      // hyp_linear output
__device__ float g_hn[NR];                          // ||h_i|| (clamped)
__device__ __align__(16) float g_sup[NR * DOUT];    // support

// ---------------- helpers ----------------
__device__ __forceinline__ float blockReduceSum128(float v, float* sred) {
    #pragma unroll
    for (int o = 16; o > 0; o >>= 1) v += __shfl_xor_sync(0xffffffffu, v, o);
    int w = threadIdx.x >> 5;
    if ((threadIdx.x & 31) == 0) sred[w] = v;
    __syncthreads();
    float r = sred[0] + sred[1] + sred[2] + sred[3];
    __syncthreads();
    return r;
}

// ---------------- K0: weight prep: hw = proj(expmap0(W,c),c) ----------------
__global__ __launch_bounds__(128) void k_prep(
    const float* __restrict__ lw, const float* __restrict__ lb,
    const float* __restrict__ aw, const float* __restrict__ ab,
    const float* __restrict__ cp)
{
    __shared__ float sred[4];
    const float c    = cp[0];
    const float sc   = sqrtf(c);
    const float maxn = (1.0f - 4e-3f) / sc;
    const int b = blockIdx.x, t = threadIdx.x;

    if (b < DOUT) {                       // hw1 rows (len 512)
        const float* u = lw + b * DIN;
        float ss = 0.f;
        #pragma unroll
        for (int i = t; i < DIN; i += 128) { float v = u[i]; ss += v * v; }
        ss = blockReduceSum128(ss, sred);
        float un = fmaxf(sqrtf(ss), 1e-15f);
        float f  = tanhf(sc * un) / (sc * un);
        float vn = fmaxf(sqrtf(f * f * ss), 1e-15f);
        float coef = f * (vn > maxn ? maxn / vn : 1.0f);
        for (int i = t; i < DIN; i += 128) g_hw1[b * DIN + i] = coef * u[i];
    } else if (b < 2 * DOUT) {            // hw2 rows (len 128)
        int r = b - DOUT;
        const float* u = aw + r * DOUT;
        float x = u[t];
        float ss = blockReduceSum128(x * x, sred);
        float un = fmaxf(sqrtf(ss), 1e-15f);
        float f  = tanhf(sc * un) / (sc * un);
        float vn = fmaxf(sqrtf(f * f * ss), 1e-15f);
        float coef = f * (vn > maxn ? maxn / vn : 1.0f);
        g_hw2[r * DOUT + t] = coef * x;
    } else {                              // hb + bias sumsq scalars
        float x = lb[t];
        float ss = blockReduceSum128(x * x, sred);
        float un = fmaxf(sqrtf(ss), 1e-15f);
        float f  = tanhf(sc * un) / (sc * un);
        float vn = fmaxf(sqrtf(f * f * ss), 1e-15f);
        float coef = f * (vn > maxn ? maxn / vn : 1.0f);
        g_hb[t] = coef * x;
        if (t == 0) g_hb2s = coef * coef * ss;
        float y = ab[t];
        float s2 = blockReduceSum128(y * y, sred);
        if (t == 0) g_b2s = s2;
    }
}

// ---------------- K0b: x row norms ----------------
__global__ __launch_bounds__(128) void k_xnorm(const float* __restrict__ x) {
    __shared__ float sred[4];
    const int r = blockIdx.x, t = threadIdx.x;
    const float* u = x + (size_t)r * DIN;
    float ss = 0.f;
    #pragma unroll
    for (int i = t; i < DIN; i += 128) { float v = u[i]; ss += v * v; }
    ss = blockReduceSum128(ss, sred);
    if (t == 0) g_xn[r] = fmaxf(sqrtf(ss), 1e-15f);
}

// ============ GEMM tile config (shared by the 3 GEMM kernels) ============
// 128 threads, BM=64, BN=128, BK=32, per-thread 8x8 micro-tile.
#define BK  32
#define BMP 68   // padded A smem stride (bank-friendly, float4-aligned)
#define BN  128

// ---------------- K1: h = hyp_linear(x,...) fused GEMM ----------------
__global__ __launch_bounds__(128) void k_lin_gemm(
    const float* __restrict__ x, const float* __restrict__ cp)
{
    __shared__ __align__(16) float pool[BK * BMP + BK * BN];
    __shared__ float par[64][2];
    __shared__ float hbv[DOUT];
    float* As = pool;
    float* Bs = pool + BK * BMP;

    const int t = threadIdx.x;
    const int rowbase = blockIdx.x * 64;
    const float c  = cp[0];
    const float sc = sqrtf(c);

    hbv[t] = g_hb[t];

    const int tr = t >> 4, tc = t & 15;
    const int ar = t >> 3, ac = (t & 7) * 4;

    float acc[8][8];
    #pragma unroll
    for (int i = 0; i < 8; i++)
        #pragma unroll
        for (int j = 0; j < 8; j++) acc[i][j] = 0.f;

    float4 la[4], lb8[8];
    #pragma unroll
    for (int p = 0; p < 4; p++)
        la[p] = *(const float4*)&x[(size_t)(rowbase + p * 16 + ar) * DIN + ac];
    #pragma unroll
    for (int f = 0; f < 8; f++)
        lb8[f] = *(const float4*)&g_hw1[t * DIN + f * 4];

    const int ITERS = DIN / BK;
    for (int it = 0; it < ITERS; ++it) {
        __syncthreads();
        #pragma unroll
        for (int p = 0; p < 4; p++) {
            float4 v = la[p]; int r = p * 16 + ar;
            As[(ac + 0) * BMP + r] = v.x; As[(ac + 1) * BMP + r] = v.y;
            As[(ac + 2) * BMP + r] = v.z; As[(ac + 3) * BMP + r] = v.w;
        }
        #pragma unroll
        for (int f = 0; f < 8; f++) {
            float4 v = lb8[f];
            Bs[(f * 4 + 0) * BN + t] = v.x; Bs[(f * 4 + 1) * BN + t] = v.y;
            Bs[(f * 4 + 2) * BN + t] = v.z; Bs[(f * 4 + 3) * BN + t] = v.w;
        }
        __syncthreads();
        if (it + 1 < ITERS) {
            int kt = (it + 1) * BK;
            #pragma unroll
            for (int p = 0; p < 4; p++)
                la[p] = *(const float4*)&x[(size_t)(rowbase + p * 16 + ar) * DIN + kt + ac];
            #pragma unroll
            for (int f = 0; f < 8; f++)
                lb8[f] = *(const float4*)&g_hw1[t * DIN + kt + f * 4];
        }
        #pragma unroll
        for (int kk = 0; kk < BK; kk++) {
            float4 a0 = *(const float4*)&As[kk * BMP + tr * 8];
            float4 a1 = *(const float4*)&As[kk * BMP + tr * 8 + 4];
            float4 b0 = *(const float4*)&Bs[kk * BN + tc * 4];
            float4 b1 = *(const float4*)&Bs[kk * BN + tc * 4 + 64];
            float av[8] = {a0.x,a0.y,a0.z,a0.w,a1.x,a1.y,a1.z,a1.w};
            float bv[8] = {b0.x,b0.y,b0.z,b0.w,b1.x,b1.y,b1.z,b1.w};
            #pragma unroll
            for (int i = 0; i < 8; i++)
                #pragma unroll
                for (int j = 0; j < 8; j++) acc[i][j] += av[i] * bv[j];
        }
    }
    __syncthreads();

    float bj[8];
    #pragma unroll
    for (int j = 0; j < 8; j++) bj[j] = hbv[(j < 4) ? tc * 4 + j : 64 + tc * 4 + (j - 4)];

    float* red = pool;  // [64][16][3]
    #pragma unroll
    for (int i = 0; i < 8; i++) {
        int r = tr * 8 + i;
        float p1 = 0.f, p2 = 0.f, p3 = 0.f;
        #pragma unroll
        for (int j = 0; j < 8; j++) {
            float v = acc[i][j];
            p1 += v * v; p2 += fabsf(v); p3 += v * bj[j];
        }
        red[(r * 16 + tc) * 3 + 0] = p1;
        red[(r * 16 + tc) * 3 + 1] = p2;
        red[(r * 16 + tc) * 3 + 2] = p3;
    }
    __syncthreads();
    if (t < 64) {
        float S1 = 0.f, S2 = 0.f, S3 = 0.f;
        #pragma unroll
        for (int q = 0; q < 16; q++) {
            S1 += red[(t * 16 + q) * 3 + 0];
            S2 += red[(t * 16 + q) * 3 + 1];
            S3 += red[(t * 16 + q) * 3 + 2];
        }
        int rowg = rowbase + t;
        float xn  = g_xn[rowg];
        float mxn = fmaxf(sqrtf(S1), 1e-15f);
        float at  = atanhf(fminf(sc * xn, 1.0f - 1e-7f));
        float s   = tanhf(mxn / xn * at) / (mxn * sc);
        if (S2 == 0.f) s = 0.f;
        float maxn = (1.0f - 4e-3f) / sc;
        float rn = fmaxf(sqrtf(s * s * S1), 1e-15f);
        if (rn > maxn) s *= maxn / rn;
        float x2 = s * s * S1;
        float xy = s * S3;
        float y2 = g_hb2s;
        float Aa = 1.0f + 2.0f * c * xy + c * y2;
        float Bb = 1.0f - c * x2;
        float den = fmaxf(1.0f + 2.0f * c * xy + c * c * x2 * y2, 1e-15f);
        float P = Aa * s / den, Q = Bb / den;
        float h2 = P * P * S1 + 2.0f * P * Q * S3 + Q * Q * y2;
        float hn = fmaxf(sqrtf(h2), 1e-15f);
        if (hn > maxn) { float g = maxn / hn; P *= g; Q *= g; hn = maxn; }
        par[t][0] = P; par[t][1] = Q;
        g_hn[rowg] = hn;
    }
    __syncthreads();
    #pragma unroll
    for (int i = 0; i < 8; i++) {
        int r = tr * 8 + i;
        float P = par[r][0], Q = par[r][1];
        float4 o0 = make_float4(P * acc[i][0] + Q * bj[0], P * acc[i][1] + Q * bj[1],
                                P * acc[i][2] + Q * bj[2], P * acc[i][3] + Q * bj[3]);
        float4 o1 = make_float4(P * acc[i][4] + Q * bj[4], P * acc[i][5] + Q * bj[5],
                                P * acc[i][6] + Q * bj[6], P * acc[i][7] + Q * bj[7]);
        *(float4*)&g_h[(size_t)(rowbase + r) * DOUT + tc * 4]      = o0;
        *(float4*)&g_h[(size_t)(rowbase + r) * DOUT + 64 + tc * 4] = o1;
    }
}

// ---------------- K2: support = mobius_matvec(hw2, h) fused GEMM ----------------
__global__ __launch_bounds__(128) void k_sup_gemm(const float* __restrict__ cp) {
    __shared__ __align__(16) float pool[BK * BMP + BK * BN];
    __shared__ float par[64];
    float* As = pool;
    float* Bs = pool + BK * BMP;

    const int t = threadIdx.x;
    const int rowbase = blockIdx.x * 64;
    const float c  = cp[0];
    const float sc = sqrtf(c);

    const int tr = t >> 4, tc = t & 15;
    const int ar = t >> 3, ac = (t & 7) * 4;

    float acc[8][8];
    #pragma unroll
    for (int i = 0; i < 8; i++)
        #pragma unroll
        for (int j = 0; j < 8; j++) acc[i][j] = 0.f;

    float4 la[4], lb8[8];
    #pragma unroll
    for (int p = 0; p < 4; p++)
        la[p] = *(const float4*)&g_h[(size_t)(rowbase + p * 16 + ar) * DOUT + ac];
    #pragma unroll
    for (int f = 0; f < 8; f++)
        lb8[f] = *(const float4*)&g_hw2[t * DOUT + f * 4];

    const int ITERS = DOUT / BK;  // 4
    for (int it = 0; it < ITERS; ++it) {
        __syncthreads();
        #pragma unroll
        for (int p = 0; p < 4; p++) {
            float4 v = la[p]; int r = p * 16 + ar;
            As[(ac + 0) * BMP + r] = v.x; As[(ac + 1) * BMP + r] = v.y;
            As[(ac + 2) * BMP + r] = v.z; As[(ac + 3) * BMP + r] = v.w;
        }
        #pragma unroll
        for (int f = 0; f < 8; f++) {
            float4 v = lb8[f];
            Bs[(f * 4 + 0) * BN + t] = v.x; Bs[(f * 4 + 1) * BN + t] = v.y;
            Bs[(f * 4 + 2) * BN + t] = v.z; Bs[(f * 4 + 3) * BN + t] = v.w;
        }
        __syncthreads();
        if (it + 1 < ITERS) {
            int kt = (it + 1) * BK;
            #pragma unroll
            for (int p = 0; p < 4; p++)
                la[p] = *(const float4*)&g_h[(size_t)(rowbase + p * 16 + ar) * DOUT + kt + ac];
            #pragma unroll
            for (int f = 0; f < 8; f++)
                lb8[f] = *(const float4*)&g_hw2[t * DOUT + kt + f * 4];
        }
        #pragma unroll
        for (int kk = 0; kk < BK; kk++) {
            float4 a0 = *(const float4*)&As[kk * BMP + tr * 8];
            float4 a1 = *(const float4*)&As[kk * BMP + tr * 8 + 4];
            float4 b0 = *(const float4*)&Bs[kk * BN + tc * 4];
            float4 b1 = *(const float4*)&Bs[kk * BN + tc * 4 + 64];
            float av[8] = {a0.x,a0.y,a0.z,a0.w,a1.x,a1.y,a1.z,a1.w};
            float bv[8] = {b0.x,b0.y,b0.z,b0.w,b1.x,b1.y,b1.z,b1.w};
            #pragma unroll
            for (int i = 0; i < 8; i++)
                #pragma unroll
                for (int j = 0; j < 8; j++) acc[i][j] += av[i] * bv[j];
        }
    }
    __syncthreads();

    float* red = pool;  // [64][16][2]
    #pragma unroll
    for (int i = 0; i < 8; i++) {
        int r = tr * 8 + i;
        float p1 = 0.f, p2 = 0.f;
        #pragma unroll
        for (int j = 0; j < 8; j++) { float v = acc[i][j]; p1 += v * v; p2 += fabsf(v); }
        red[(r * 16 + tc) * 2 + 0] = p1;
        red[(r * 16 + tc) * 2 + 1] = p2;
    }
    __syncthreads();
    if (t < 64) {
        float S1 = 0.f, S2 = 0.f;
        #pragma unroll
        for (int q = 0; q < 16; q++) {
            S1 += red[(t * 16 + q) * 2 + 0];
            S2 += red[(t * 16 + q) * 2 + 1];
        }
        float hn  = g_hn[rowbase + t];
        float mxn = fmaxf(sqrtf(S1), 1e-15f);
        float at  = atanhf(fminf(sc * hn, 1.0f - 1e-7f));
        float s   = tanhf(mxn / hn * at) / (mxn * sc);
        if (S2 == 0.f) s = 0.f;
        par[t] = s;
    }
    __syncthreads();
    #pragma unroll
    for (int i = 0; i < 8; i++) {
        int r = tr * 8 + i;
        float s = par[r];
        float4 o0 = make_float4(s*acc[i][0], s*acc[i][1], s*acc[i][2], s*acc[i][3]);
        float4 o1 = make_float4(s*acc[i][4], s*acc[i][5], s*acc[i][6], s*acc[i][7]);
        *(float4*)&g_sup[(size_t)(rowbase + r) * DOUT + tc * 4]      = o0;
        *(float4*)&g_sup[(size_t)(rowbase + r) * DOUT + 64 + tc * 4] = o1;
    }
}

// ---------------- K3: out = hyp_act(proj(mobius_add(_mfm(adj@sup, adj), b))) ----------------
__global__ __launch_bounds__(128) void k_agg_gemm(
    const float* __restrict__ adj, const float* __restrict__ bias,
    const float* __restrict__ cp, float* __restrict__ out)
{
    __shared__ __align__(16) float pool[BK * BMP + BK * BN];
    __shared__ float par[64][4];
    __shared__ float bvec[DOUT];
    __shared__ float arow[64];
    float* As = pool;
    float* Bs = pool + BK * BMP;

    const int t = threadIdx.x;
    const int rowbase = blockIdx.x * 64;
    const float c  = cp[0];
    const float sc = sqrtf(c);

    bvec[t] = bias[t];

    const int tr = t >> 4, tc = t & 15;
    const int ar = t >> 3, ac = (t & 7) * 4;   // A load mapping (row fixed per thread)
    const int br = t >> 5, bc = (t & 31) * 4;  // B load mapping

    float acc[8][8];
    #pragma unroll
    for (int i = 0; i < 8; i++)
        #pragma unroll
        for (int j = 0; j < 8; j++) acc[i][j] = 0.f;

    float4 la[4], lbv[8];
    float asq[4] = {0.f, 0.f, 0.f, 0.f};

    #pragma unroll
    for (int p = 0; p < 4; p++)
        la[p] = *(const float4*)&adj[(size_t)(rowbase + p * 16 + ar) * NR + ac];
    #pragma unroll
    for (int p = 0; p < 8; p++)
        lbv[p] = *(const float4*)&g_sup[(size_t)(p * 4 + br) * DOUT + bc];

    const int ITERS = NR / BK;  // 256
    for (int it = 0; it < ITERS; ++it) {
        __syncthreads();
        #pragma unroll
        for (int p = 0; p < 4; p++) {
            float4 v = la[p]; int r = p * 16 + ar;
            As[(ac + 0) * BMP + r] = v.x; As[(ac + 1) * BMP + r] = v.y;
            As[(ac + 2) * BMP + r] = v.z; As[(ac + 3) * BMP + r] = v.w;
            asq[p] += v.x * v.x + v.y * v.y + v.z * v.z + v.w * v.w;
        }
        #pragma unroll
        for (int p = 0; p < 8; p++)
            *(float4*)&Bs[(p * 4 + br) * BN + bc] = lbv[p];
        __syncthreads();
        if (it + 1 < ITERS) {
            int kt = (it + 1) * BK;
            #pragma unroll
            for (int p = 0; p < 4; p++)
                la[p] = *(const float4*)&adj[(size_t)(rowbase + p * 16 + ar) * NR + kt + ac];
            #pragma unroll
            for (int p = 0; p < 8; p++)
                lbv[p] = *(const float4*)&g_sup[(size_t)(kt + p * 4 + br) * DOUT + bc];
        }
        #pragma unroll
        for (int kk = 0; kk < BK; kk++) {
            float4 a0 = *(const float4*)&As[kk * BMP + tr * 8];
            float4 a1 = *(const float4*)&As[kk * BMP + tr * 8 + 4];
            float4 b0 = *(const float4*)&Bs[kk * BN + tc * 4];
            float4 b1 = *(const float4*)&Bs[kk * BN + tc * 4 + 64];
            float av[8] = {a0.x,a0.y,a0.z,a0.w,a1.x,a1.y,a1.z,a1.w};
            float bv[8] = {b0.x,b0.y,b0.z,b0.w,b1.x,b1.y,b1.z,b1.w};
            #pragma unroll
            for (int i = 0; i < 8; i++)
                #pragma unroll
                for (int j = 0; j < 8; j++) acc[i][j] += av[i] * bv[j];
        }
    }
    __syncthreads();

    // adj row sum-of-squares: reduce across the 8 loader-lanes per row
    #pragma unroll
    for (int p = 0; p < 4; p++) {
        float v = asq[p];
        v += __shfl_xor_sync(0xffffffffu, v, 1);
        v += __shfl_xor_sync(0xffffffffu, v, 2);
        v += __shfl_xor_sync(0xffffffffu, v, 4);
        if ((t & 7) == 0) arow[p * 16 + ar] = v;
    }

    float bj[8];
    #pragma unroll
    for (int j = 0; j < 8; j++) bj[j] = bvec[(j < 4) ? tc * 4 + j : 64 + tc * 4 + (j - 4)];

    float* red = pool;  // [64][16][3]
    #pragma unroll
    for (int i = 0; i < 8; i++) {
        int r = tr * 8 + i;
        float p1 = 0.f, p2 = 0.f, p3 = 0.f;
        #pragma unroll
        for (int j = 0; j < 8; j++) {
            float v = acc[i][j];
            p1 += v * v; p2 += fabsf(v); p3 += v * bj[j];
        }
        red[(r * 16 + tc) * 3 + 0] = p1;
        red[(r * 16 + tc) * 3 + 1] = p2;
        red[(r * 16 + tc) * 3 + 2] = p3;
    }
    __syncthreads();
    if (t < 64) {
        float S1 = 0.f, S2 = 0.f, S3 = 0.f;
        #pragma unroll
        for (int q = 0; q < 16; q++) {
            S1 += red[(t * 16 + q) * 3 + 0];
            S2 += red[(t * 16 + q) * 3 + 1];
            S3 += red[(t * 16 + q) * 3 + 2];
        }
        float an  = fmaxf(sqrtf(arow[t]), 1e-15f);
        float mxn = fmaxf(sqrtf(S1), 1e-15f);
        float at  = atanhf(fminf(sc * an, 1.0f - 1e-7f));
        float s   = tanhf(mxn / an * at) / (mxn * sc);
        if (S2 == 0.f) s = 0.f;
        float x2 = s * s * S1;
        float xy = s * S3;
        float y2 = g_b2s;
        float Aa = 1.0f + 2.0f * c * xy + c * y2;
        float Bb = 1.0f - c * x2;
        float den = fmaxf(1.0f + 2.0f * c * xy + c * c * x2 * y2, 1e-15f);
        float P = Aa * s / den, Q = Bb / den;
        float g2 = P * P * S1 + 2.0f * P * Q * S3 + Q * Q * y2;
        float gn = fmaxf(sqrtf(g2), 1e-15f);
        float maxn = (1.0f - 4e-3f) / sc;
        if (gn > maxn) { float g = maxn / gn; P *= g; Q *= g; gn = maxn; }
        float L = atanhf(fminf(sc * gn, 1.0f - 1e-7f)) / (gn * sc);  // logmap0 coefficient
        par[t][0] = P; par[t][1] = Q; par[t][2] = L;
    }
    __syncthreads();
    // leaky_relu(logmap0(...)) in registers + second reduction for expmap0
    #pragma unroll
    for (int i = 0; i < 8; i++) {
        int r = tr * 8 + i;
        float P = par[r][0], Q = par[r][1], L = par[r][2];
        float q2 = 0.f;
        #pragma unroll
        for (int j = 0; j < 8; j++) {
            float v = L * (P * acc[i][j] + Q * bj[j]);
            v = (v >= 0.f) ? v : 0.01f * v;
            acc[i][j] = v;
            q2 += v * v;
        }
        red[r * 16 + tc] = q2;
    }
    __syncthreads();
    if (t < 64) {
        float u2 = 0.f;
        #pragma unroll
        for (int q = 0; q < 16; q++) u2 += red[t * 16 + q];
        float un  = fmaxf(sqrtf(u2), 1e-15f);
        // FIX: expmap0 uses curvature c (sqrt(c)); only the proj bound uses 1-c.
        float e   = tanhf(sc * un) / (sc * un);
        float vn  = fmaxf(sqrtf(e * e * u2), 1e-15f);
        float sc2 = sqrtf(1.0f - c);
        float mn2 = (1.0f - 4e-3f) / sc2;
        if (vn > mn2) e *= mn2 / vn;
        par[t][3] = e;
    }
    __syncthreads();
    #pragma unroll
    for (int i = 0; i < 8; i++) {
        int r = tr * 8 + i;
        float e = par[r][3];
        float4 o0 = make_float4(e*acc[i][0], e*acc[i][1], e*acc[i][2], e*acc[i][3]);
        float4 o1 = make_float4(e*acc[i][4], e*acc[i][5], e*acc[i][6], e*acc[i][7]);
        *(float4*)&out[(size_t)(rowbase + r) * DOUT + tc * 4]      = o0;
        *(float4*)&out[(size_t)(rowbase + r) * DOUT + 64 + tc * 4] = o1;
    }
}

// ---------------- launch ----------------
extern "C" void kernel_launch(void* const* d_in, const int* in_sizes, int n_in,
                              void* d_out, int out_size)
{
    const float* x   = (const float*)d_in[0];
    const float* adj = (const float*)d_in[1];
    const float* cp  = (const float*)d_in[2];
    const float* lw  = (const float*)d_in[3];
    const float* lb  = (const float*)d_in[4];
    const float* aw  = (const float*)d_in[5];
    const float* ab  = (const float*)d_in[6];
    float* out = (float*)d_out;

    k_prep<<<2 * DOUT + 1, 128>>>(lw, lb, aw, ab, cp);
    k_xnorm<<<NR, 128>>>(x);
    k_lin_gemm<<<NR / 64, 128>>>(x, cp);
    k_sup_gemm<<<NR / 64, 128>>>(cp);
    k_agg_gemm<<<NR / 64, 128>>>(adj, ab, cp, out);
}

// round 7
// speedup vs baseline: 2.2683x; 2.2683x over previous
#include <cuda_runtime.h>
#include <cstdint>

// Problem dims (fixed for this problem instance)
#define NR   8192   // rows (nodes)
#define DIN  512    // input feature dim
#define DOUT 128    // output feature dim

// ---------------- scratch (static device globals; no allocation) ----------------
__device__ __align__(16) float g_hw1[DOUT * DIN];   // proj(expmap0(lin_weight))
__device__ __align__(16) float g_hw2[DOUT * DOUT];  // proj(expmap0(agg_weight))
__device__ __align__(16) float g_hb[DOUT];          // proj(expmap0(lin_bias))
__device__ float g_hb2s;                            // sum hb^2
__device__ float g_b2s;                             // sum agg_bias^2
__device__ float g_xn[NR];                          // ||x_i|| (clamped)
__device__ __align__(16) float g_h[NR * DOUT];      // hyp_linear output
__device__ float g_hn[NR];                          // ||h_i|| (clamped)
__device__ __align__(16) float g_sup[NR * DOUT];    // support
__device__ __align__(16) float g_supT[DOUT * NR];   // support^T, tf32-rounded values

// ---------------- baseline-PTX helpers (no sm_103a-only instructions) ----------------
__device__ __forceinline__ uint32_t smem_u32(const void* p) {
    uint32_t a;
    asm("{ .reg .u64 t; cvta.to.shared.u64 t, %1; cvt.u32.u64 %0, t; }" : "=r"(a) : "l"(p));
    return a;
}
__device__ __forceinline__ uint32_t f2tf32(float x) {
    uint32_t r;
    asm("cvt.rna.tf32.f32 %0, %1;" : "=r"(r) : "f"(x));
    return r;
}
__device__ __forceinline__ void cp_async16(uint32_t dst_smem, const void* src) {
    asm volatile("cp.async.cg.shared.global [%0], [%1], 16;" :: "r"(dst_smem), "l"(src) : "memory");
}
#define CP_COMMIT() asm volatile("cp.async.commit_group;" ::: "memory")
#define CP_WAIT0()  asm volatile("cp.async.wait_group 0;" ::: "memory")

// m16n8k8 tf32 MMA (compute_80 baseline feature; legacy HMMA on Blackwell)
__device__ __forceinline__ void mma_tf32(float* d,
                                         uint32_t a0, uint32_t a1, uint32_t a2, uint32_t a3,
                                         uint32_t b0, uint32_t b1) {
    asm volatile(
        "mma.sync.aligned.m16n8k8.row.col.f32.tf32.tf32.f32 "
        "{%0,%1,%2,%3}, {%4,%5,%6,%7}, {%8,%9}, {%0,%1,%2,%3};"
        : "+f"(d[0]), "+f"(d[1]), "+f"(d[2]), "+f"(d[3])
        : "r"(a0), "r"(a1), "r"(a2), "r"(a3), "r"(b0), "r"(b1));
}

// ---------------- helpers ----------------
__device__ __forceinline__ float blockReduceSum128(float v, float* sred) {
    #pragma unroll
    for (int o = 16; o > 0; o >>= 1) v += __shfl_xor_sync(0xffffffffu, v, o);
    int w = threadIdx.x >> 5;
    if ((threadIdx.x & 31) == 0) sred[w] = v;
    __syncthreads();
    float r = sred[0] + sred[1] + sred[2] + sred[3];
    __syncthreads();
    return r;
}

// ---------------- K0: weight prep: hw = proj(expmap0(W,c),c) ----------------
__global__ __launch_bounds__(128) void k_prep(
    const float* __restrict__ lw, const float* __restrict__ lb,
    const float* __restrict__ aw, const float* __restrict__ ab,
    const float* __restrict__ cp)
{
    __shared__ float sred[4];
    const float c    = cp[0];
    const float sc   = sqrtf(c);
    const float maxn = (1.0f - 4e-3f) / sc;
    const int b = blockIdx.x, t = threadIdx.x;

    if (b < DOUT) {                       // hw1 rows (len 512)
        const float* u = lw + b * DIN;
        float ss = 0.f;
        #pragma unroll
        for (int i = t; i < DIN; i += 128) { float v = u[i]; ss += v * v; }
        ss = blockReduceSum128(ss, sred);
        float un = fmaxf(sqrtf(ss), 1e-15f);
        float f  = tanhf(sc * un) / (sc * un);
        float vn = fmaxf(sqrtf(f * f * ss), 1e-15f);
        float coef = f * (vn > maxn ? maxn / vn : 1.0f);
        for (int i = t; i < DIN; i += 128) g_hw1[b * DIN + i] = coef * u[i];
    } else if (b < 2 * DOUT) {            // hw2 rows (len 128)
        int r = b - DOUT;
        const float* u = aw + r * DOUT;
        float x = u[t];
        float ss = blockReduceSum128(x * x, sred);
        float un = fmaxf(sqrtf(ss), 1e-15f);
        float f  = tanhf(sc * un) / (sc * un);
        float vn = fmaxf(sqrtf(f * f * ss), 1e-15f);
        float coef = f * (vn > maxn ? maxn / vn : 1.0f);
        g_hw2[r * DOUT + t] = coef * x;
    } else {                              // hb + bias sumsq scalars
        float x = lb[t];
        float ss = blockReduceSum128(x * x, sred);
        float un = fmaxf(sqrtf(ss), 1e-15f);
        float f  = tanhf(sc * un) / (sc * un);
        float vn = fmaxf(sqrtf(f * f * ss), 1e-15f);
        float coef = f * (vn > maxn ? maxn / vn : 1.0f);
        g_hb[t] = coef * x;
        if (t == 0) g_hb2s = coef * coef * ss;
        float y = ab[t];
        float s2 = blockReduceSum128(y * y, sred);
        if (t == 0) g_b2s = s2;
    }
}

// ---------------- K0b: x row norms ----------------
__global__ __launch_bounds__(128) void k_xnorm(const float* __restrict__ x) {
    __shared__ float sred[4];
    const int r = blockIdx.x, t = threadIdx.x;
    const float* u = x + (size_t)r * DIN;
    float ss = 0.f;
    #pragma unroll
    for (int i = t; i < DIN; i += 128) { float v = u[i]; ss += v * v; }
    ss = blockReduceSum128(ss, sred);
    if (t == 0) g_xn[r] = fmaxf(sqrtf(ss), 1e-15f);
}

// ============ FFMA GEMM tile config (K1, K2) ============
#define BK  32
#define BMP 68
#define BN  128

// ---------------- K1: h = hyp_linear(x,...) fused GEMM ----------------
__global__ __launch_bounds__(128) void k_lin_gemm(
    const float* __restrict__ x, const float* __restrict__ cp)
{
    __shared__ __align__(16) float pool[BK * BMP + BK * BN];
    __shared__ float par[64][2];
    __shared__ float hbv[DOUT];
    float* As = pool;
    float* Bs = pool + BK * BMP;

    const int t = threadIdx.x;
    const int rowbase = blockIdx.x * 64;
    const float c  = cp[0];
    const float sc = sqrtf(c);

    hbv[t] = g_hb[t];

    const int tr = t >> 4, tc = t & 15;
    const int ar = t >> 3, ac = (t & 7) * 4;

    float acc[8][8];
    #pragma unroll
    for (int i = 0; i < 8; i++)
        #pragma unroll
        for (int j = 0; j < 8; j++) acc[i][j] = 0.f;

    float4 la[4], lb8[8];
    #pragma unroll
    for (int p = 0; p < 4; p++)
        la[p] = *(const float4*)&x[(size_t)(rowbase + p * 16 + ar) * DIN + ac];
    #pragma unroll
    for (int f = 0; f < 8; f++)
        lb8[f] = *(const float4*)&g_hw1[t * DIN + f * 4];

    const int ITERS = DIN / BK;
    for (int it = 0; it < ITERS; ++it) {
        __syncthreads();
        #pragma unroll
        for (int p = 0; p < 4; p++) {
            float4 v = la[p]; int r = p * 16 + ar;
            As[(ac + 0) * BMP + r] = v.x; As[(ac + 1) * BMP + r] = v.y;
            As[(ac + 2) * BMP + r] = v.z; As[(ac + 3) * BMP + r] = v.w;
        }
        #pragma unroll
        for (int f = 0; f < 8; f++) {
            float4 v = lb8[f];
            Bs[(f * 4 + 0) * BN + t] = v.x; Bs[(f * 4 + 1) * BN + t] = v.y;
            Bs[(f * 4 + 2) * BN + t] = v.z; Bs[(f * 4 + 3) * BN + t] = v.w;
        }
        __syncthreads();
        if (it + 1 < ITERS) {
            int kt = (it + 1) * BK;
            #pragma unroll
            for (int p = 0; p < 4; p++)
                la[p] = *(const float4*)&x[(size_t)(rowbase + p * 16 + ar) * DIN + kt + ac];
            #pragma unroll
            for (int f = 0; f < 8; f++)
                lb8[f] = *(const float4*)&g_hw1[t * DIN + kt + f * 4];
        }
        #pragma unroll
        for (int kk = 0; kk < BK; kk++) {
            float4 a0 = *(const float4*)&As[kk * BMP + tr * 8];
            float4 a1 = *(const float4*)&As[kk * BMP + tr * 8 + 4];
            float4 b0 = *(const float4*)&Bs[kk * BN + tc * 4];
            float4 b1 = *(const float4*)&Bs[kk * BN + tc * 4 + 64];
            float av[8] = {a0.x,a0.y,a0.z,a0.w,a1.x,a1.y,a1.z,a1.w};
            float bv[8] = {b0.x,b0.y,b0.z,b0.w,b1.x,b1.y,b1.z,b1.w};
            #pragma unroll
            for (int i = 0; i < 8; i++)
                #pragma unroll
                for (int j = 0; j < 8; j++) acc[i][j] += av[i] * bv[j];
        }
    }
    __syncthreads();

    float bj[8];
    #pragma unroll
    for (int j = 0; j < 8; j++) bj[j] = hbv[(j < 4) ? tc * 4 + j : 64 + tc * 4 + (j - 4)];

    float* red = pool;  // [64][16][3]
    #pragma unroll
    for (int i = 0; i < 8; i++) {
        int r = tr * 8 + i;
        float p1 = 0.f, p2 = 0.f, p3 = 0.f;
        #pragma unroll
        for (int j = 0; j < 8; j++) {
            float v = acc[i][j];
            p1 += v * v; p2 += fabsf(v); p3 += v * bj[j];
        }
        red[(r * 16 + tc) * 3 + 0] = p1;
        red[(r * 16 + tc) * 3 + 1] = p2;
        red[(r * 16 + tc) * 3 + 2] = p3;
    }
    __syncthreads();
    if (t < 64) {
        float S1 = 0.f, S2 = 0.f, S3 = 0.f;
        #pragma unroll
        for (int q = 0; q < 16; q++) {
            S1 += red[(t * 16 + q) * 3 + 0];
            S2 += red[(t * 16 + q) * 3 + 1];
            S3 += red[(t * 16 + q) * 3 + 2];
        }
        int rowg = rowbase + t;
        float xn  = g_xn[rowg];
        float mxn = fmaxf(sqrtf(S1), 1e-15f);
        float at  = atanhf(fminf(sc * xn, 1.0f - 1e-7f));
        float s   = tanhf(mxn / xn * at) / (mxn * sc);
        if (S2 == 0.f) s = 0.f;
        float maxn = (1.0f - 4e-3f) / sc;
        float rn = fmaxf(sqrtf(s * s * S1), 1e-15f);
        if (rn > maxn) s *= maxn / rn;
        float x2 = s * s * S1;
        float xy = s * S3;
        float y2 = g_hb2s;
        float Aa = 1.0f + 2.0f * c * xy + c * y2;
        float Bb = 1.0f - c * x2;
        float den = fmaxf(1.0f + 2.0f * c * xy + c * c * x2 * y2, 1e-15f);
        float P = Aa * s / den, Q = Bb / den;
        float h2 = P * P * S1 + 2.0f * P * Q * S3 + Q * Q * y2;
        float hn = fmaxf(sqrtf(h2), 1e-15f);
        if (hn > maxn) { float g = maxn / hn; P *= g; Q *= g; hn = maxn; }
        par[t][0] = P; par[t][1] = Q;
        g_hn[rowg] = hn;
    }
    __syncthreads();
    #pragma unroll
    for (int i = 0; i < 8; i++) {
        int r = tr * 8 + i;
        float P = par[r][0], Q = par[r][1];
        float4 o0 = make_float4(P * acc[i][0] + Q * bj[0], P * acc[i][1] + Q * bj[1],
                                P * acc[i][2] + Q * bj[2], P * acc[i][3] + Q * bj[3]);
        float4 o1 = make_float4(P * acc[i][4] + Q * bj[4], P * acc[i][5] + Q * bj[5],
                                P * acc[i][6] + Q * bj[6], P * acc[i][7] + Q * bj[7]);
        *(float4*)&g_h[(size_t)(rowbase + r) * DOUT + tc * 4]      = o0;
        *(float4*)&g_h[(size_t)(rowbase + r) * DOUT + 64 + tc * 4] = o1;
    }
}

// ---------------- K2: support = mobius_matvec(hw2, h) fused GEMM ----------------
__global__ __launch_bounds__(128) void k_sup_gemm(const float* __restrict__ cp) {
    __shared__ __align__(16) float pool[BK * BMP + BK * BN];
    __shared__ float par[64];
    float* As = pool;
    float* Bs = pool + BK * BMP;

    const int t = threadIdx.x;
    const int rowbase = blockIdx.x * 64;
    const float c  = cp[0];
    const float sc = sqrtf(c);

    const int tr = t >> 4, tc = t & 15;
    const int ar = t >> 3, ac = (t & 7) * 4;

    float acc[8][8];
    #pragma unroll
    for (int i = 0; i < 8; i++)
        #pragma unroll
        for (int j = 0; j < 8; j++) acc[i][j] = 0.f;

    float4 la[4], lb8[8];
    #pragma unroll
    for (int p = 0; p < 4; p++)
        la[p] = *(const float4*)&g_h[(size_t)(rowbase + p * 16 + ar) * DOUT + ac];
    #pragma unroll
    for (int f = 0; f < 8; f++)
        lb8[f] = *(const float4*)&g_hw2[t * DOUT + f * 4];

    const int ITERS = DOUT / BK;  // 4
    for (int it = 0; it < ITERS; ++it) {
        __syncthreads();
        #pragma unroll
        for (int p = 0; p < 4; p++) {
            float4 v = la[p]; int r = p * 16 + ar;
            As[(ac + 0) * BMP + r] = v.x; As[(ac + 1) * BMP + r] = v.y;
            As[(ac + 2) * BMP + r] = v.z; As[(ac + 3) * BMP + r] = v.w;
        }
        #pragma unroll
        for (int f = 0; f < 8; f++) {
            float4 v = lb8[f];
            Bs[(f * 4 + 0) * BN + t] = v.x; Bs[(f * 4 + 1) * BN + t] = v.y;
            Bs[(f * 4 + 2) * BN + t] = v.z; Bs[(f * 4 + 3) * BN + t] = v.w;
        }
        __syncthreads();
        if (it + 1 < ITERS) {
            int kt = (it + 1) * BK;
            #pragma unroll
            for (int p = 0; p < 4; p++)
                la[p] = *(const float4*)&g_h[(size_t)(rowbase + p * 16 + ar) * DOUT + kt + ac];
            #pragma unroll
            for (int f = 0; f < 8; f++)
                lb8[f] = *(const float4*)&g_hw2[t * DOUT + kt + f * 4];
        }
        #pragma unroll
        for (int kk = 0; kk < BK; kk++) {
            float4 a0 = *(const float4*)&As[kk * BMP + tr * 8];
            float4 a1 = *(const float4*)&As[kk * BMP + tr * 8 + 4];
            float4 b0 = *(const float4*)&Bs[kk * BN + tc * 4];
            float4 b1 = *(const float4*)&Bs[kk * BN + tc * 4 + 64];
            float av[8] = {a0.x,a0.y,a0.z,a0.w,a1.x,a1.y,a1.z,a1.w};
            float bv[8] = {b0.x,b0.y,b0.z,b0.w,b1.x,b1.y,b1.z,b1.w};
            #pragma unroll
            for (int i = 0; i < 8; i++)
                #pragma unroll
                for (int j = 0; j < 8; j++) acc[i][j] += av[i] * bv[j];
        }
    }
    __syncthreads();

    float* red = pool;  // [64][16][2]
    #pragma unroll
    for (int i = 0; i < 8; i++) {
        int r = tr * 8 + i;
        float p1 = 0.f, p2 = 0.f;
        #pragma unroll
        for (int j = 0; j < 8; j++) { float v = acc[i][j]; p1 += v * v; p2 += fabsf(v); }
        red[(r * 16 + tc) * 2 + 0] = p1;
        red[(r * 16 + tc) * 2 + 1] = p2;
    }
    __syncthreads();
    if (t < 64) {
        float S1 = 0.f, S2 = 0.f;
        #pragma unroll
        for (int q = 0; q < 16; q++) {
            S1 += red[(t * 16 + q) * 2 + 0];
            S2 += red[(t * 16 + q) * 2 + 1];
        }
        float hn  = g_hn[rowbase + t];
        float mxn = fmaxf(sqrtf(S1), 1e-15f);
        float at  = atanhf(fminf(sc * hn, 1.0f - 1e-7f));
        float s   = tanhf(mxn / hn * at) / (mxn * sc);
        if (S2 == 0.f) s = 0.f;
        par[t] = s;
    }
    __syncthreads();
    #pragma unroll
    for (int i = 0; i < 8; i++) {
        int r = tr * 8 + i;
        float s = par[r];
        float4 o0 = make_float4(s*acc[i][0], s*acc[i][1], s*acc[i][2], s*acc[i][3]);
        float4 o1 = make_float4(s*acc[i][4], s*acc[i][5], s*acc[i][6], s*acc[i][7]);
        *(float4*)&g_sup[(size_t)(rowbase + r) * DOUT + tc * 4]      = o0;
        *(float4*)&g_sup[(size_t)(rowbase + r) * DOUT + 64 + tc * 4] = o1;
    }
}

// ---------------- K2b: transpose support -> g_supT[feat][row], tf32-rounded ----------------
__global__ __launch_bounds__(256) void k_transpose() {
    __shared__ float tile[32][33];
    const int bx = blockIdx.x;           // row tile (NR/32 = 256)
    const int by = blockIdx.y;           // feat tile (DOUT/32 = 4)
    const int tx = threadIdx.x & 31, ty = threadIdx.x >> 5;  // 32x8
    #pragma unroll
    for (int i = 0; i < 4; i++)
        tile[ty + 8 * i][tx] = g_sup[(size_t)(bx * 32 + ty + 8 * i) * DOUT + by * 32 + tx];
    __syncthreads();
    #pragma unroll
    for (int i = 0; i < 4; i++) {
        uint32_t tv = f2tf32(tile[tx][ty + 8 * i]);
        g_supT[(size_t)(by * 32 + ty + 8 * i) * NR + bx * 32 + tx] = __uint_as_float(tv);
    }
}

// ---------------- K3: tf32 mma.sync adj@sup + fused hyperbolic epilogue ----------------
// 128 CTAs x 128 threads. CTA: M=64 x N=128, K=8192 chunked by 32, double-buffered.
// smem rows stride 36 floats (36 % 32 == 4 -> conflict-free fragment LDS).
#define KC    32
#define NCH   (NR / KC)      // 256
#define ASTR  36
#define BSTR  36
#define A_FL  (64 * ASTR)    // 2304 floats per A buffer
#define B_FL  (128 * BSTR)   // 4608 floats per B buffer
#define K3_SMEM ((256 + 2 * A_FL + 2 * B_FL) * 4)  // 56320 bytes

__global__ __launch_bounds__(128) void k_agg_mma(
    const float* __restrict__ adj, const float* __restrict__ bias,
    const float* __restrict__ cp, float* __restrict__ out)
{
    extern __shared__ __align__(16) float dsm[];
    float* bv   = dsm;          // [128]
    float* arow = dsm + 128;    // [64]
    float* Ab   = dsm + 256;                 // 2 x A_FL
    float* Bb   = dsm + 256 + 2 * A_FL;      // 2 x B_FL

    const int t = threadIdx.x;
    const int w = t >> 5, l = t & 31;
    const int qr = l >> 2, qc = l & 3;
    const int rowbase = blockIdx.x * 64;
    const float c  = cp[0];
    const float sc = sqrtf(c);

    bv[t] = bias[t];

    // A loader mapping: 2 threads per row, 16 floats each
    const int lrow = t >> 1;               // 0..63
    const int lk4  = (t & 1) * 4;          // float4 sub-offset within chunk
    const float4* ap = (const float4*)(adj + (size_t)(rowbase + lrow) * NR);
    const uint32_t bb_u = smem_u32(Bb);
    const float* bsrc = g_supT + (size_t)t * NR;

    float acc[16][4];
    #pragma unroll
    for (int i = 0; i < 16; i++)
        #pragma unroll
        for (int j = 0; j < 4; j++) acc[i][j] = 0.f;

    float asq = 0.f;
    float4 la[4];

    // -------- prologue: chunk 0 into buffer 0 --------
    #pragma unroll
    for (int i = 0; i < 4; i++) la[i] = ap[lk4 + i];
    #pragma unroll
    for (int i = 0; i < 4; i++) {
        float4 v = la[i];
        asq += v.x*v.x + v.y*v.y + v.z*v.z + v.w*v.w;
        uint4 u = make_uint4(f2tf32(v.x), f2tf32(v.y), f2tf32(v.z), f2tf32(v.w));
        *(uint4*)&Ab[lrow * ASTR + lk4 * 4 + i * 4] = u;
    }
    #pragma unroll
    for (int i = 0; i < 8; i++)
        cp_async16(bb_u + (uint32_t)(t * BSTR + i * 4) * 4, bsrc + i * 4);
    CP_COMMIT();
    CP_WAIT0();
    __syncthreads();

    // -------- main K loop --------
    for (int ck = 0; ck < NCH; ++ck) {
        const int cur = ck & 1, nxt = cur ^ 1;
        const bool more = (ck + 1 < NCH);
        if (more) {
            const int f4 = (ck + 1) * 8 + lk4;
            #pragma unroll
            for (int i = 0; i < 4; i++) la[i] = ap[f4 + i];
            const float* bs = bsrc + (ck + 1) * KC;
            #pragma unroll
            for (int i = 0; i < 8; i++)
                cp_async16(bb_u + (uint32_t)(nxt * B_FL + t * BSTR + i * 4) * 4, bs + i * 4);
            CP_COMMIT();
        }
        // MMA over current buffer
        {
            const float* As  = Ab + cur * A_FL + (w * 16) * ASTR;
            const float* Bsp = Bb + cur * B_FL;
            #pragma unroll
            for (int ks = 0; ks < 4; ks++) {
                const int k0 = ks * 8;
                uint32_t a0 = __float_as_uint(As[qr * ASTR + k0 + qc]);
                uint32_t a1 = __float_as_uint(As[(qr + 8) * ASTR + k0 + qc]);
                uint32_t a2 = __float_as_uint(As[qr * ASTR + k0 + qc + 4]);
                uint32_t a3 = __float_as_uint(As[(qr + 8) * ASTR + k0 + qc + 4]);
                #pragma unroll
                for (int nt = 0; nt < 16; nt++) {
                    uint32_t b0 = __float_as_uint(Bsp[(nt * 8 + qr) * BSTR + k0 + qc]);
                    uint32_t b1 = __float_as_uint(Bsp[(nt * 8 + qr) * BSTR + k0 + qc + 4]);
                    mma_tf32(acc[nt], a0, a1, a2, a3, b0, b1);
                }
            }
        }
        if (more) {
            #pragma unroll
            for (int i = 0; i < 4; i++) {
                float4 v = la[i];
                asq += v.x*v.x + v.y*v.y + v.z*v.z + v.w*v.w;
                uint4 u = make_uint4(f2tf32(v.x), f2tf32(v.y), f2tf32(v.z), f2tf32(v.w));
                *(uint4*)&Ab[nxt * A_FL + lrow * ASTR + lk4 * 4 + i * 4] = u;
            }
            CP_WAIT0();
        }
        __syncthreads();
    }

    // adj row sumsq: combine 2 loader threads per row
    asq += __shfl_xor_sync(0xffffffffu, asq, 1);
    if ((t & 1) == 0) arow[lrow] = asq;
    __syncthreads();

    // -------- fragment-domain hyperbolic epilogue --------
    // lane owns rows r0 = w*16+qr, r1 = r0+8 (CTA-local); cols nt*8 + 2*qc (+1)
    float S1[2] = {0.f, 0.f}, S2[2] = {0.f, 0.f}, S3[2] = {0.f, 0.f};
    #pragma unroll
    for (int nt = 0; nt < 16; nt++) {
        const int col = nt * 8 + 2 * qc;
        const float b0 = bv[col], b1 = bv[col + 1];
        float c0 = acc[nt][0], c1 = acc[nt][1], c2 = acc[nt][2], c3 = acc[nt][3];
        S1[0] += c0*c0 + c1*c1;  S2[0] += fabsf(c0) + fabsf(c1);  S3[0] += c0*b0 + c1*b1;
        S1[1] += c2*c2 + c3*c3;  S2[1] += fabsf(c2) + fabsf(c3);  S3[1] += c2*b0 + c3*b1;
    }
    #pragma unroll
    for (int r = 0; r < 2; r++) {
        S1[r] += __shfl_xor_sync(0xffffffffu, S1[r], 1);
        S1[r] += __shfl_xor_sync(0xffffffffu, S1[r], 2);
        S2[r] += __shfl_xor_sync(0xffffffffu, S2[r], 1);
        S2[r] += __shfl_xor_sync(0xffffffffu, S2[r], 2);
        S3[r] += __shfl_xor_sync(0xffffffffu, S3[r], 1);
        S3[r] += __shfl_xor_sync(0xffffffffu, S3[r], 2);
    }

    float Pr[2], Qr[2], Lr[2];
    const float y2 = g_b2s;
    const float maxn = (1.0f - 4e-3f) / sc;
    #pragma unroll
    for (int r = 0; r < 2; r++) {
        const int rl = w * 16 + qr + r * 8;
        float an  = fmaxf(sqrtf(arow[rl]), 1e-15f);
        float mxn = fmaxf(sqrtf(S1[r]), 1e-15f);
        float at  = atanhf(fminf(sc * an, 1.0f - 1e-7f));
        float s   = tanhf(mxn / an * at) / (mxn * sc);
        if (S2[r] == 0.f) s = 0.f;
        float x2 = s * s * S1[r];
        float xy = s * S3[r];
        float Aa = 1.0f + 2.0f * c * xy + c * y2;
        float Bb2 = 1.0f - c * x2;
        float den = fmaxf(1.0f + 2.0f * c * xy + c * c * x2 * y2, 1e-15f);
        float P = Aa * s / den, Q = Bb2 / den;
        float g2 = P * P * S1[r] + 2.0f * P * Q * S3[r] + Q * Q * y2;
        float gn = fmaxf(sqrtf(g2), 1e-15f);
        if (gn > maxn) { float g = maxn / gn; P *= g; Q *= g; gn = maxn; }
        Pr[r] = P; Qr[r] = Q;
        Lr[r] = atanhf(fminf(sc * gn, 1.0f - 1e-7f)) / (gn * sc);
    }

    float q2[2] = {0.f, 0.f};
    #pragma unroll
    for (int nt = 0; nt < 16; nt++) {
        const int col = nt * 8 + 2 * qc;
        const float b0 = bv[col], b1 = bv[col + 1];
        float v0 = Lr[0] * (Pr[0] * acc[nt][0] + Qr[0] * b0);
        float v1 = Lr[0] * (Pr[0] * acc[nt][1] + Qr[0] * b1);
        float v2 = Lr[1] * (Pr[1] * acc[nt][2] + Qr[1] * b0);
        float v3 = Lr[1] * (Pr[1] * acc[nt][3] + Qr[1] * b1);
        v0 = (v0 >= 0.f) ? v0 : 0.01f * v0;
        v1 = (v1 >= 0.f) ? v1 : 0.01f * v1;
        v2 = (v2 >= 0.f) ? v2 : 0.01f * v2;
        v3 = (v3 >= 0.f) ? v3 : 0.01f * v3;
        acc[nt][0] = v0; acc[nt][1] = v1; acc[nt][2] = v2; acc[nt][3] = v3;
        q2[0] += v0*v0 + v1*v1;
        q2[1] += v2*v2 + v3*v3;
    }
    float er[2];
    const float sc2 = sqrtf(1.0f - c);
    const float mn2 = (1.0f - 4e-3f) / sc2;
    #pragma unroll
    for (int r = 0; r < 2; r++) {
        q2[r] += __shfl_xor_sync(0xffffffffu, q2[r], 1);
        q2[r] += __shfl_xor_sync(0xffffffffu, q2[r], 2);
        float un = fmaxf(sqrtf(q2[r]), 1e-15f);
        float e  = tanhf(sc * un) / (sc * un);      // expmap0 with curvature c
        float vn = fmaxf(sqrtf(e * e * q2[r]), 1e-15f);
        if (vn > mn2) e *= mn2 / vn;                // proj with curvature 1-c
        er[r] = e;
    }

    const int g0 = rowbase + w * 16 + qr;
    #pragma unroll
    for (int nt = 0; nt < 16; nt++) {
        const int col = nt * 8 + 2 * qc;
        *(float2*)&out[(size_t)g0 * DOUT + col] =
            make_float2(er[0] * acc[nt][0], er[0] * acc[nt][1]);
        *(float2*)&out[(size_t)(g0 + 8) * DOUT + col] =
            make_float2(er[1] * acc[nt][2], er[1] * acc[nt][3]);
    }
}

// ---------------- launch ----------------
extern "C" void kernel_launch(void* const* d_in, const int* in_sizes, int n_in,
                              void* d_out, int out_size)
{
    const float* x   = (const float*)d_in[0];
    const float* adj = (const float*)d_in[1];
    const float* cp  = (const float*)d_in[2];
    const float* lw  = (const float*)d_in[3];
    const float* lb  = (const float*)d_in[4];
    const float* aw  = (const float*)d_in[5];
    const float* ab  = (const float*)d_in[6];
    float* out = (float*)d_out;

    cudaFuncSetAttribute(k_agg_mma, cudaFuncAttributeMaxDynamicSharedMemorySize, K3_SMEM);

    k_prep<<<2 * DOUT + 1, 128>>>(lw, lb, aw, ab, cp);
    k_xnorm<<<NR, 128>>>(x);
    k_lin_gemm<<<NR / 64, 128>>>(x, cp);
    k_sup_gemm<<<NR / 64, 128>>>(cp);
    k_transpose<<<dim3(NR / 32, DOUT / 32), 256>>>();
    k_agg_mma<<<NR / 64, 128, K3_SMEM>>>(adj, ab, cp, out);
}

// round 10
// speedup vs baseline: 2.8205x; 1.2434x over previous
#include <cuda_runtime.h>
#include <cuda_bf16.h>
#include <cstdint>

// Problem dims (fixed for this problem instance)
#define NR   8192   // rows (nodes)
#define DIN  512    // input feature dim
#define DOUT 128    // output feature dim

// ---------------- scratch (static device globals; no allocation) ----------------
__device__ __align__(16) float g_hw1[DOUT * DIN];   // proj(expmap0(lin_weight))
__device__ __align__(16) float g_hw2[DOUT * DOUT];  // proj(expmap0(agg_weight))
__device__ __align__(16) float g_hb[DOUT];          // proj(expmap0(lin_bias))
__device__ float g_hb2s;                            // sum hb^2
__device__ float g_b2s;                             // sum agg_bias^2
__device__ float g_xn[NR];                          // ||x_i|| (clamped)
__device__ __align__(16) float g_h[NR * DOUT];      // hyp_linear output
__device__ float g_hn[NR];                          // ||h_i|| (clamped)
__device__ __align__(16) __nv_bfloat16 g_supb[NR * DOUT];  // support, bf16, node-major

// ---------------- baseline-PTX helpers (no sm_103a-only instructions) ----------------
__device__ __forceinline__ uint32_t smem_u32(const void* p) {
    uint32_t a;
    asm("{ .reg .u64 t; cvta.to.shared.u64 t, %1; cvt.u32.u64 %0, t; }" : "=r"(a) : "l"(p));
    return a;
}
__device__ __forceinline__ uint32_t pack_bf16(float lo, float hi) {
    uint32_t r;
    asm("cvt.rn.bf16x2.f32 %0, %1, %2;" : "=r"(r) : "f"(hi), "f"(lo));
    return r;
}
__device__ __forceinline__ void cp_async16(uint32_t dst_smem, const void* src) {
    asm volatile("cp.async.cg.shared.global [%0], [%1], 16;" :: "r"(dst_smem), "l"(src) : "memory");
}
#define CP_COMMIT() asm volatile("cp.async.commit_group;" ::: "memory")
#define CP_WAIT0()  asm volatile("cp.async.wait_group 0;" ::: "memory")

#define LDSM_X4(r0, r1, r2, r3, addr) \
    asm volatile("ldmatrix.sync.aligned.m8n8.x4.shared.b16 {%0,%1,%2,%3}, [%4];" \
        : "=r"(r0), "=r"(r1), "=r"(r2), "=r"(r3) : "r"(addr))
#define LDSM_X4T(r0, r1, r2, r3, addr) \
    asm volatile("ldmatrix.sync.aligned.m8n8.x4.trans.shared.b16 {%0,%1,%2,%3}, [%4];" \
        : "=r"(r0), "=r"(r1), "=r"(r2), "=r"(r3) : "r"(addr))

// m16n8k16 bf16 MMA (compute_80 baseline feature)
__device__ __forceinline__ void mma_bf16(float* d,
                                         uint32_t a0, uint32_t a1, uint32_t a2, uint32_t a3,
                                         uint32_t b0, uint32_t b1) {
    asm volatile(
        "mma.sync.aligned.m16n8k16.row.col.f32.bf16.bf16.f32 "
        "{%0,%1,%2,%3}, {%4,%5,%6,%7}, {%8,%9}, {%0,%1,%2,%3};"
        : "+f"(d[0]), "+f"(d[1]), "+f"(d[2]), "+f"(d[3])
        : "r"(a0), "r"(a1), "r"(a2), "r"(a3), "r"(b0), "r"(b1));
}

// ---------------- helpers ----------------
__device__ __forceinline__ float blockReduceSum128(float v, float* sred) {
    #pragma unroll
    for (int o = 16; o > 0; o >>= 1) v += __shfl_xor_sync(0xffffffffu, v, o);
    int w = threadIdx.x >> 5;
    if ((threadIdx.x & 31) == 0) sred[w] = v;
    __syncthreads();
    float r = sred[0] + sred[1] + sred[2] + sred[3];
    __syncthreads();
    return r;
}

// ---------------- K0: weight prep: hw = proj(expmap0(W,c),c) ----------------
__global__ __launch_bounds__(128) void k_prep(
    const float* __restrict__ lw, const float* __restrict__ lb,
    const float* __restrict__ aw, const float* __restrict__ ab,
    const float* __restrict__ cp)
{
    __shared__ float sred[4];
    const float c    = cp[0];
    const float sc   = sqrtf(c);
    const float maxn = (1.0f - 4e-3f) / sc;
    const int b = blockIdx.x, t = threadIdx.x;

    if (b < DOUT) {                       // hw1 rows (len 512)
        const float* u = lw + b * DIN;
        float ss = 0.f;
        #pragma unroll
        for (int i = t; i < DIN; i += 128) { float v = u[i]; ss += v * v; }
        ss = blockReduceSum128(ss, sred);
        float un = fmaxf(sqrtf(ss), 1e-15f);
        float f  = tanhf(sc * un) / (sc * un);
        float vn = fmaxf(sqrtf(f * f * ss), 1e-15f);
        float coef = f * (vn > maxn ? maxn / vn : 1.0f);
        for (int i = t; i < DIN; i += 128) g_hw1[b * DIN + i] = coef * u[i];
    } else if (b < 2 * DOUT) {            // hw2 rows (len 128)
        int r = b - DOUT;
        const float* u = aw + r * DOUT;
        float x = u[t];
        float ss = blockReduceSum128(x * x, sred);
        float un = fmaxf(sqrtf(ss), 1e-15f);
        float f  = tanhf(sc * un) / (sc * un);
        float vn = fmaxf(sqrtf(f * f * ss), 1e-15f);
        float coef = f * (vn > maxn ? maxn / vn : 1.0f);
        g_hw2[r * DOUT + t] = coef * x;
    } else {                              // hb + bias sumsq scalars
        float x = lb[t];
        float ss = blockReduceSum128(x * x, sred);
        float un = fmaxf(sqrtf(ss), 1e-15f);
        float f  = tanhf(sc * un) / (sc * un);
        float vn = fmaxf(sqrtf(f * f * ss), 1e-15f);
        float coef = f * (vn > maxn ? maxn / vn : 1.0f);
        g_hb[t] = coef * x;
        if (t == 0) g_hb2s = coef * coef * ss;
        float y = ab[t];
        float s2 = blockReduceSum128(y * y, sred);
        if (t == 0) g_b2s = s2;
    }
}

// ---------------- K0b: x row norms ----------------
__global__ __launch_bounds__(128) void k_xnorm(const float* __restrict__ x) {
    __shared__ float sred[4];
    const int r = blockIdx.x, t = threadIdx.x;
    const float* u = x + (size_t)r * DIN;
    float ss = 0.f;
    #pragma unroll
    for (int i = t; i < DIN; i += 128) { float v = u[i]; ss += v * v; }
    ss = blockReduceSum128(ss, sred);
    if (t == 0) g_xn[r] = fmaxf(sqrtf(ss), 1e-15f);
}

// ============ FFMA GEMM tile config (K1, K2) ============
#define BK  32
#define BMP 68
#define BN  128

// ---------------- K1: h = hyp_linear(x,...) fused GEMM ----------------
__global__ __launch_bounds__(128) void k_lin_gemm(
    const float* __restrict__ x, const float* __restrict__ cp)
{
    __shared__ __align__(16) float pool[BK * BMP + BK * BN];
    __shared__ float par[64][2];
    __shared__ float hbv[DOUT];
    float* As = pool;
    float* Bs = pool + BK * BMP;

    const int t = threadIdx.x;
    const int rowbase = blockIdx.x * 64;
    const float c  = cp[0];
    const float sc = sqrtf(c);

    hbv[t] = g_hb[t];

    const int tr = t >> 4, tc = t & 15;
    const int ar = t >> 3, ac = (t & 7) * 4;

    float acc[8][8];
    #pragma unroll
    for (int i = 0; i < 8; i++)
        #pragma unroll
        for (int j = 0; j < 8; j++) acc[i][j] = 0.f;

    float4 la[4], lb8[8];
    #pragma unroll
    for (int p = 0; p < 4; p++)
        la[p] = *(const float4*)&x[(size_t)(rowbase + p * 16 + ar) * DIN + ac];
    #pragma unroll
    for (int f = 0; f < 8; f++)
        lb8[f] = *(const float4*)&g_hw1[t * DIN + f * 4];

    const int ITERS = DIN / BK;
    for (int it = 0; it < ITERS; ++it) {
        __syncthreads();
        #pragma unroll
        for (int p = 0; p < 4; p++) {
            float4 v = la[p]; int r = p * 16 + ar;
            As[(ac + 0) * BMP + r] = v.x; As[(ac + 1) * BMP + r] = v.y;
            As[(ac + 2) * BMP + r] = v.z; As[(ac + 3) * BMP + r] = v.w;
        }
        #pragma unroll
        for (int f = 0; f < 8; f++) {
            float4 v = lb8[f];
            Bs[(f * 4 + 0) * BN + t] = v.x; Bs[(f * 4 + 1) * BN + t] = v.y;
            Bs[(f * 4 + 2) * BN + t] = v.z; Bs[(f * 4 + 3) * BN + t] = v.w;
        }
        __syncthreads();
        if (it + 1 < ITERS) {
            int kt = (it + 1) * BK;
            #pragma unroll
            for (int p = 0; p < 4; p++)
                la[p] = *(const float4*)&x[(size_t)(rowbase + p * 16 + ar) * DIN + kt + ac];
            #pragma unroll
            for (int f = 0; f < 8; f++)
                lb8[f] = *(const float4*)&g_hw1[t * DIN + kt + f * 4];
        }
        #pragma unroll
        for (int kk = 0; kk < BK; kk++) {
            float4 a0 = *(const float4*)&As[kk * BMP + tr * 8];
            float4 a1 = *(const float4*)&As[kk * BMP + tr * 8 + 4];
            float4 b0 = *(const float4*)&Bs[kk * BN + tc * 4];
            float4 b1 = *(const float4*)&Bs[kk * BN + tc * 4 + 64];
            float av[8] = {a0.x,a0.y,a0.z,a0.w,a1.x,a1.y,a1.z,a1.w};
            float bv[8] = {b0.x,b0.y,b0.z,b0.w,b1.x,b1.y,b1.z,b1.w};
            #pragma unroll
            for (int i = 0; i < 8; i++)
                #pragma unroll
                for (int j = 0; j < 8; j++) acc[i][j] += av[i] * bv[j];
        }
    }
    __syncthreads();

    float bj[8];
    #pragma unroll
    for (int j = 0; j < 8; j++) bj[j] = hbv[(j < 4) ? tc * 4 + j : 64 + tc * 4 + (j - 4)];

    float* red = pool;  // [64][16][3]
    #pragma unroll
    for (int i = 0; i < 8; i++) {
        int r = tr * 8 + i;
        float p1 = 0.f, p2 = 0.f, p3 = 0.f;
        #pragma unroll
        for (int j = 0; j < 8; j++) {
            float v = acc[i][j];
            p1 += v * v; p2 += fabsf(v); p3 += v * bj[j];
        }
        red[(r * 16 + tc) * 3 + 0] = p1;
        red[(r * 16 + tc) * 3 + 1] = p2;
        red[(r * 16 + tc) * 3 + 2] = p3;
    }
    __syncthreads();
    if (t < 64) {
        float S1 = 0.f, S2 = 0.f, S3 = 0.f;
        #pragma unroll
        for (int q = 0; q < 16; q++) {
            S1 += red[(t * 16 + q) * 3 + 0];
            S2 += red[(t * 16 + q) * 3 + 1];
            S3 += red[(t * 16 + q) * 3 + 2];
        }
        int rowg = rowbase + t;
        float xn  = g_xn[rowg];
        float mxn = fmaxf(sqrtf(S1), 1e-15f);
        float at  = atanhf(fminf(sc * xn, 1.0f - 1e-7f));
        float s   = tanhf(mxn / xn * at) / (mxn * sc);
        if (S2 == 0.f) s = 0.f;
        float maxn = (1.0f - 4e-3f) / sc;
        float rn = fmaxf(sqrtf(s * s * S1), 1e-15f);
        if (rn > maxn) s *= maxn / rn;
        float x2 = s * s * S1;
        float xy = s * S3;
        float y2 = g_hb2s;
        float Aa = 1.0f + 2.0f * c * xy + c * y2;
        float Bb = 1.0f - c * x2;
        float den = fmaxf(1.0f + 2.0f * c * xy + c * c * x2 * y2, 1e-15f);
        float P = Aa * s / den, Q = Bb / den;
        float h2 = P * P * S1 + 2.0f * P * Q * S3 + Q * Q * y2;
        float hn = fmaxf(sqrtf(h2), 1e-15f);
        if (hn > maxn) { float g = maxn / hn; P *= g; Q *= g; hn = maxn; }
        par[t][0] = P; par[t][1] = Q;
        g_hn[rowg] = hn;
    }
    __syncthreads();
    #pragma unroll
    for (int i = 0; i < 8; i++) {
        int r = tr * 8 + i;
        float P = par[r][0], Q = par[r][1];
        float4 o0 = make_float4(P * acc[i][0] + Q * bj[0], P * acc[i][1] + Q * bj[1],
                                P * acc[i][2] + Q * bj[2], P * acc[i][3] + Q * bj[3]);
        float4 o1 = make_float4(P * acc[i][4] + Q * bj[4], P * acc[i][5] + Q * bj[5],
                                P * acc[i][6] + Q * bj[6], P * acc[i][7] + Q * bj[7]);
        *(float4*)&g_h[(size_t)(rowbase + r) * DOUT + tc * 4]      = o0;
        *(float4*)&g_h[(size_t)(rowbase + r) * DOUT + 64 + tc * 4] = o1;
    }
}

// ---------------- K2: support = mobius_matvec(hw2, h) fused GEMM -> bf16 ----------------
__global__ __launch_bounds__(128) void k_sup_gemm(const float* __restrict__ cp) {
    __shared__ __align__(16) float pool[BK * BMP + BK * BN];
    __shared__ float par[64];
    float* As = pool;
    float* Bs = pool + BK * BMP;

    const int t = threadIdx.x;
    const int rowbase = blockIdx.x * 64;
    const float c  = cp[0];
    const float sc = sqrtf(c);

    const int tr = t >> 4, tc = t & 15;
    const int ar = t >> 3, ac = (t & 7) * 4;

    float acc[8][8];
    #pragma unroll
    for (int i = 0; i < 8; i++)
        #pragma unroll
        for (int j = 0; j < 8; j++) acc[i][j] = 0.f;

    float4 la[4], lb8[8];
    #pragma unroll
    for (int p = 0; p < 4; p++)
        la[p] = *(const float4*)&g_h[(size_t)(rowbase + p * 16 + ar) * DOUT + ac];
    #pragma unroll
    for (int f = 0; f < 8; f++)
        lb8[f] = *(const float4*)&g_hw2[t * DOUT + f * 4];

    const int ITERS = DOUT / BK;  // 4
    for (int it = 0; it < ITERS; ++it) {
        __syncthreads();
        #pragma unroll
        for (int p = 0; p < 4; p++) {
            float4 v = la[p]; int r = p * 16 + ar;
            As[(ac + 0) * BMP + r] = v.x; As[(ac + 1) * BMP + r] = v.y;
            As[(ac + 2) * BMP + r] = v.z; As[(ac + 3) * BMP + r] = v.w;
        }
        #pragma unroll
        for (int f = 0; f < 8; f++) {
            float4 v = lb8[f];
            Bs[(f * 4 + 0) * BN + t] = v.x; Bs[(f * 4 + 1) * BN + t] = v.y;
            Bs[(f * 4 + 2) * BN + t] = v.z; Bs[(f * 4 + 3) * BN + t] = v.w;
        }
        __syncthreads();
        if (it + 1 < ITERS) {
            int kt = (it + 1) * BK;
            #pragma unroll
            for (int p = 0; p < 4; p++)
                la[p] = *(const float4*)&g_h[(size_t)(rowbase + p * 16 + ar) * DOUT + kt + ac];
            #pragma unroll
            for (int f = 0; f < 8; f++)
                lb8[f] = *(const float4*)&g_hw2[t * DOUT + kt + f * 4];
        }
        #pragma unroll
        for (int kk = 0; kk < BK; kk++) {
            float4 a0 = *(const float4*)&As[kk * BMP + tr * 8];
            float4 a1 = *(const float4*)&As[kk * BMP + tr * 8 + 4];
            float4 b0 = *(const float4*)&Bs[kk * BN + tc * 4];
            float4 b1 = *(const float4*)&Bs[kk * BN + tc * 4 + 64];
            float av[8] = {a0.x,a0.y,a0.z,a0.w,a1.x,a1.y,a1.z,a1.w};
            float bv[8] = {b0.x,b0.y,b0.z,b0.w,b1.x,b1.y,b1.z,b1.w};
            #pragma unroll
            for (int i = 0; i < 8; i++)
                #pragma unroll
                for (int j = 0; j < 8; j++) acc[i][j] += av[i] * bv[j];
        }
    }
    __syncthreads();

    float* red = pool;  // [64][16][2]
    #pragma unroll
    for (int i = 0; i < 8; i++) {
        int r = tr * 8 + i;
        float p1 = 0.f, p2 = 0.f;
        #pragma unroll
        for (int j = 0; j < 8; j++) { float v = acc[i][j]; p1 += v * v; p2 += fabsf(v); }
        red[(r * 16 + tc) * 2 + 0] = p1;
        red[(r * 16 + tc) * 2 + 1] = p2;
    }
    __syncthreads();
    if (t < 64) {
        float S1 = 0.f, S2 = 0.f;
        #pragma unroll
        for (int q = 0; q < 16; q++) {
            S1 += red[(t * 16 + q) * 2 + 0];
            S2 += red[(t * 16 + q) * 2 + 1];
        }
        float hn  = g_hn[rowbase + t];
        float mxn = fmaxf(sqrtf(S1), 1e-15f);
        float at  = atanhf(fminf(sc * hn, 1.0f - 1e-7f));
        float s   = tanhf(mxn / hn * at) / (mxn * sc);
        if (S2 == 0.f) s = 0.f;
        par[t] = s;
    }
    __syncthreads();
    #pragma unroll
    for (int i = 0; i < 8; i++) {
        int r = tr * 8 + i;
        float s = par[r];
        uint32_t u0 = pack_bf16(s * acc[i][0], s * acc[i][1]);
        uint32_t u1 = pack_bf16(s * acc[i][2], s * acc[i][3]);
        uint32_t u2 = pack_bf16(s * acc[i][4], s * acc[i][5]);
        uint32_t u3 = pack_bf16(s * acc[i][6], s * acc[i][7]);
        *(uint2*)&g_supb[(size_t)(rowbase + r) * DOUT + tc * 4]      = make_uint2(u0, u1);
        *(uint2*)&g_supb[(size_t)(rowbase + r) * DOUT + 64 + tc * 4] = make_uint2(u2, u3);
    }
}

// ---------------- K3: bf16 mma.sync adj@sup + fused hyperbolic epilogue ----------------
// 128 CTAs x 256 threads (8 warps). CTA: M=64 x N=128, K=8192 chunked by 32, double-buffered.
// Warp w: m-band (w&3)*16, n-half (w>>2)*64.
// A smem [m=64][k=32] bf16, row stride 80 B (pad) -> ldmatrix conflict-free.
// B smem [k=32][n=128] bf16, row stride 272 B (pad) -> ldmatrix.trans conflict-free.
#define KC      32
#define NCH     (NR / KC)     // 256
#define ASTR_B  80
#define BSTR_B  272
#define A_BYTES (64 * ASTR_B)   // 5120
#define B_BYTES (32 * BSTR_B)   // 8704

__global__ __launch_bounds__(256) void k_agg_mma(
    const float* __restrict__ adj, const float* __restrict__ bias,
    const float* __restrict__ cp, float* __restrict__ out)
{
    __shared__ __align__(16) char Ab[2][A_BYTES];
    __shared__ __align__(16) char Bb[2][B_BYTES];
    __shared__ float bv[128];
    __shared__ float arow[64];
    __shared__ float sredS[64][2][3];
    __shared__ float sredQ[64][2];

    const int t = threadIdx.x;
    const int w = t >> 5, l = t & 31;
    const int mb = (w & 3) * 16;      // warp m-band
    const int nhalf = w >> 2;         // warp n-half (0/1)
    const int rowbase = blockIdx.x * 64;
    const float c  = cp[0];
    const float sc = sqrtf(c);

    if (t < 128) bv[t] = bias[t];

    // A loader: thread t -> adj row t>>2, 8-float slice (t&3)
    const int arI = t >> 2, aq = t & 3;
    const float4* ap = (const float4*)(adj + (size_t)(rowbase + arI) * NR);
    // B loader: thread t -> sup k-row t>>3, two 16B chunks at (t&7)*2
    const int bkr = t >> 3, bc2 = (t & 7) * 2;

    const uint32_t abase = smem_u32(Ab);
    const uint32_t bbase = smem_u32(Bb);

    float acc[8][4];
    #pragma unroll
    for (int i = 0; i < 8; i++)
        #pragma unroll
        for (int j = 0; j < 4; j++) acc[i][j] = 0.f;

    float asq = 0.f;
    float4 la0, la1;

    // -------- prologue: chunk 0 into buffer 0 --------
    la0 = ap[aq * 2]; la1 = ap[aq * 2 + 1];
    asq += la0.x*la0.x + la0.y*la0.y + la0.z*la0.z + la0.w*la0.w
         + la1.x*la1.x + la1.y*la1.y + la1.z*la1.z + la1.w*la1.w;
    {
        uint4 u = make_uint4(pack_bf16(la0.x, la0.y), pack_bf16(la0.z, la0.w),
                             pack_bf16(la1.x, la1.y), pack_bf16(la1.z, la1.w));
        *(uint4*)&Ab[0][arI * ASTR_B + aq * 16] = u;
    }
    #pragma unroll
    for (int i = 0; i < 2; i++)
        cp_async16(bbase + (uint32_t)(bkr * BSTR_B + (bc2 + i) * 16),
                   (const char*)g_supb + ((size_t)bkr * DOUT + (bc2 + i) * 8) * 2);
    CP_COMMIT();
    CP_WAIT0();
    __syncthreads();

    // -------- main K loop --------
    for (int ck = 0; ck < NCH; ++ck) {
        const int cur = ck & 1, nxt = cur ^ 1;
        const bool more = (ck + 1 < NCH);
        if (more) {
            la0 = ap[(ck + 1) * 8 + aq * 2];
            la1 = ap[(ck + 1) * 8 + aq * 2 + 1];
            #pragma unroll
            for (int i = 0; i < 2; i++)
                cp_async16(bbase + (uint32_t)(nxt * B_BYTES + bkr * BSTR_B + (bc2 + i) * 16),
                           (const char*)g_supb + ((size_t)((ck + 1) * KC + bkr) * DOUT + (bc2 + i) * 8) * 2);
            CP_COMMIT();
        }
        // MMA over current buffer
        {
            const uint32_t aT = abase + (uint32_t)cur * A_BYTES;
            const uint32_t bT = bbase + (uint32_t)cur * B_BYTES;
            #pragma unroll
            for (int ks = 0; ks < 2; ks++) {
                uint32_t a0, a1, a2, a3;
                uint32_t aaddr = aT + (uint32_t)((mb + (l & 15)) * ASTR_B + ks * 32 + (l >> 4) * 16);
                LDSM_X4(a0, a1, a2, a3, aaddr);
                #pragma unroll
                for (int p = 0; p < 4; p++) {
                    uint32_t b0, b1, b2, b3;
                    uint32_t baddr = bT + (uint32_t)((ks * 16 + (l & 15)) * BSTR_B
                                   + nhalf * 128 + (2 * p + (l >> 4)) * 16);
                    LDSM_X4T(b0, b1, b2, b3, baddr);
                    mma_bf16(acc[2 * p],     a0, a1, a2, a3, b0, b1);
                    mma_bf16(acc[2 * p + 1], a0, a1, a2, a3, b2, b3);
                }
            }
        }
        if (more) {
            asq += la0.x*la0.x + la0.y*la0.y + la0.z*la0.z + la0.w*la0.w
                 + la1.x*la1.x + la1.y*la1.y + la1.z*la1.z + la1.w*la1.w;
            uint4 u = make_uint4(pack_bf16(la0.x, la0.y), pack_bf16(la0.z, la0.w),
                                 pack_bf16(la1.x, la1.y), pack_bf16(la1.z, la1.w));
            *(uint4*)&Ab[nxt][arI * ASTR_B + aq * 16] = u;
            CP_WAIT0();
        }
        __syncthreads();
    }

    // adj row sumsq: combine 4 loader threads per row
    asq += __shfl_xor_sync(0xffffffffu, asq, 1);
    asq += __shfl_xor_sync(0xffffffffu, asq, 2);
    if ((t & 3) == 0) arow[arI] = asq;
    __syncthreads();

    // -------- fragment-domain hyperbolic epilogue (N split across warp pairs) --------
    // lane rows: r0 = mb + (l>>2), r1 = r0 + 8; cols: nhalf*64 + nt*8 + 2*(l&3)+{0,1}
    float S1[2] = {0.f, 0.f}, S2[2] = {0.f, 0.f}, S3[2] = {0.f, 0.f};
    #pragma unroll
    for (int nt = 0; nt < 8; nt++) {
        const int col = nhalf * 64 + nt * 8 + 2 * (l & 3);
        const float b0 = bv[col], b1 = bv[col + 1];
        float c0 = acc[nt][0], c1 = acc[nt][1], c2 = acc[nt][2], c3 = acc[nt][3];
        S1[0] += c0*c0 + c1*c1;  S2[0] += fabsf(c0) + fabsf(c1);  S3[0] += c0*b0 + c1*b1;
        S1[1] += c2*c2 + c3*c3;  S2[1] += fabsf(c2) + fabsf(c3);  S3[1] += c2*b0 + c3*b1;
    }
    #pragma unroll
    for (int r = 0; r < 2; r++) {
        S1[r] += __shfl_xor_sync(0xffffffffu, S1[r], 1);
        S1[r] += __shfl_xor_sync(0xffffffffu, S1[r], 2);
        S2[r] += __shfl_xor_sync(0xffffffffu, S2[r], 1);
        S2[r] += __shfl_xor_sync(0xffffffffu, S2[r], 2);
        S3[r] += __shfl_xor_sync(0xffffffffu, S3[r], 1);
        S3[r] += __shfl_xor_sync(0xffffffffu, S3[r], 2);
    }
    if ((l & 3) == 0) {
        const int r0 = mb + (l >> 2);
        sredS[r0][nhalf][0] = S1[0]; sredS[r0][nhalf][1] = S2[0]; sredS[r0][nhalf][2] = S3[0];
        sredS[r0 + 8][nhalf][0] = S1[1]; sredS[r0 + 8][nhalf][1] = S2[1]; sredS[r0 + 8][nhalf][2] = S3[1];
    }
    __syncthreads();

    float Pr[2], Qr[2], Lr[2];
    const float y2 = g_b2s;
    const float maxn = (1.0f - 4e-3f) / sc;
    #pragma unroll
    for (int r = 0; r < 2; r++) {
        const int rl = mb + (l >> 2) + r * 8;
        float S1t = sredS[rl][0][0] + sredS[rl][1][0];
        float S2t = sredS[rl][0][1] + sredS[rl][1][1];
        float S3t = sredS[rl][0][2] + sredS[rl][1][2];
        float an  = fmaxf(sqrtf(arow[rl]), 1e-15f);
        float mxn = fmaxf(sqrtf(S1t), 1e-15f);
        float at  = atanhf(fminf(sc * an, 1.0f - 1e-7f));
        float s   = tanhf(mxn / an * at) / (mxn * sc);
        if (S2t == 0.f) s = 0.f;
        float x2 = s * s * S1t;
        float xy = s * S3t;
        float Aa = 1.0f + 2.0f * c * xy + c * y2;
        float Bb2 = 1.0f - c * x2;
        float den = fmaxf(1.0f + 2.0f * c * xy + c * c * x2 * y2, 1e-15f);
        float P = Aa * s / den, Q = Bb2 / den;
        float g2 = P * P * S1t + 2.0f * P * Q * S3t + Q * Q * y2;
        float gn = fmaxf(sqrtf(g2), 1e-15f);
        if (gn > maxn) { float g = maxn / gn; P *= g; Q *= g; gn = maxn; }
        Pr[r] = P; Qr[r] = Q;
        Lr[r] = atanhf(fminf(sc * gn, 1.0f - 1e-7f)) / (gn * sc);
    }

    float q2[2] = {0.f, 0.f};
    #pragma unroll
    for (int nt = 0; nt < 8; nt++) {
        const int col = nhalf * 64 + nt * 8 + 2 * (l & 3);
        const float b0 = bv[col], b1 = bv[col + 1];
        float v0 = Lr[0] * (Pr[0] * acc[nt][0] + Qr[0] * b0);
        float v1 = Lr[0] * (Pr[0] * acc[nt][1] + Qr[0] * b1);
        float v2 = Lr[1] * (Pr[1] * acc[nt][2] + Qr[1] * b0);
        float v3 = Lr[1] * (Pr[1] * acc[nt][3] + Qr[1] * b1);
        v0 = (v0 >= 0.f) ? v0 : 0.01f * v0;
        v1 = (v1 >= 0.f) ? v1 : 0.01f * v1;
        v2 = (v2 >= 0.f) ? v2 : 0.01f * v2;
        v3 = (v3 >= 0.f) ? v3 : 0.01f * v3;
        acc[nt][0] = v0; acc[nt][1] = v1; acc[nt][2] = v2; acc[nt][3] = v3;
        q2[0] += v0*v0 + v1*v1;
        q2[1] += v2*v2 + v3*v3;
    }
    #pragma unroll
    for (int r = 0; r < 2; r++) {
        q2[r] += __shfl_xor_sync(0xffffffffu, q2[r], 1);
        q2[r] += __shfl_xor_sync(0xffffffffu, q2[r], 2);
    }
    if ((l & 3) == 0) {
        const int r0 = mb + (l >> 2);
        sredQ[r0][nhalf] = q2[0];
        sredQ[r0 + 8][nhalf] = q2[1];
    }
    __syncthreads();

    float er[2];
    const float sc2 = sqrtf(1.0f - c);
    const float mn2 = (1.0f - 4e-3f) / sc2;
    #pragma unroll
    for (int r = 0; r < 2; r++) {
        const int rl = mb + (l >> 2) + r * 8;
        float q2t = sredQ[rl][0] + sredQ[rl][1];
        float un = fmaxf(sqrtf(q2t), 1e-15f);
        float e  = tanhf(sc * un) / (sc * un);      // expmap0 with curvature c
        float vn = fmaxf(sqrtf(e * e * q2t), 1e-15f);
        if (vn > mn2) e *= mn2 / vn;                // proj with curvature 1-c
        er[r] = e;
    }

    const int g0 = rowbase + mb + (l >> 2);
    #pragma unroll
    for (int nt = 0; nt < 8; nt++) {
        const int col = nhalf * 64 + nt * 8 + 2 * (l & 3);
        *(float2*)&out[(size_t)g0 * DOUT + col] =
            make_float2(er[0] * acc[nt][0], er[0] * acc[nt][1]);
        *(float2*)&out[(size_t)(g0 + 8) * DOUT + col] =
            make_float2(er[1] * acc[nt][2], er[1] * acc[nt][3]);
    }
}

// ---------------- launch ----------------
extern "C" void kernel_launch(void* const* d_in, const int* in_sizes, int n_in,
                              void* d_out, int out_size)
{
    const float* x   = (const float*)d_in[0];
    const float* adj = (const float*)d_in[1];
    const float* cp  = (const float*)d_in[2];
    const float* lw  = (const float*)d_in[3];
    const float* lb  = (const float*)d_in[4];
    const float* aw  = (const float*)d_in[5];
    const float* ab  = (const float*)d_in[6];
    float* out = (float*)d_out;

    k_prep<<<2 * DOUT + 1, 128>>>(lw, lb, aw, ab, cp);
    k_xnorm<<<NR, 128>>>(x);
    k_lin_gemm<<<NR / 64, 128>>>(x, cp);
    k_sup_gemm<<<NR / 64, 128>>>(cp);
    k_agg_mma<<<NR / 64, 256>>>(adj, ab, cp, out);
}

// round 11
// speedup vs baseline: 4.5738x; 1.6217x over previous
#include <cuda_runtime.h>
#include <cuda_bf16.h>
#include <cstdint>

// Problem dims (fixed for this problem instance)
#define NR   8192   // rows (nodes)
#define DIN  512    // input feature dim
#define DOUT 128    // output feature dim

// ---------------- scratch (static device globals; no allocation) ----------------
__device__ __align__(16) __nv_bfloat16 g_hw1b[DIN * DOUT]; // proj(expmap0(lin_weight))^T, bf16 [k][n]
__device__ __align__(16) float g_hw2[DOUT * DOUT];  // proj(expmap0(agg_weight))
__device__ __align__(16) float g_hb[DOUT];          // proj(expmap0(lin_bias))
__device__ float g_hb2s;                            // sum hb^2
__device__ float g_b2s;                             // sum agg_bias^2
__device__ __align__(16) float g_h[NR * DOUT];      // hyp_linear output
__device__ float g_hn[NR];                          // ||h_i|| (clamped)
__device__ __align__(16) __nv_bfloat16 g_supb[NR * DOUT];  // support, bf16, node-major

// ---------------- baseline-PTX helpers (no sm_103a-only instructions) ----------------
__device__ __forceinline__ uint32_t smem_u32(const void* p) {
    uint32_t a;
    asm("{ .reg .u64 t; cvta.to.shared.u64 t, %1; cvt.u32.u64 %0, t; }" : "=r"(a) : "l"(p));
    return a;
}
__device__ __forceinline__ uint32_t pack_bf16(float lo, float hi) {
    uint32_t r;
    asm("cvt.rn.bf16x2.f32 %0, %1, %2;" : "=r"(r) : "f"(hi), "f"(lo));
    return r;
}
__device__ __forceinline__ void cp_async16(uint32_t dst_smem, const void* src) {
    asm volatile("cp.async.cg.shared.global [%0], [%1], 16;" :: "r"(dst_smem), "l"(src) : "memory");
}
#define CP_COMMIT() asm volatile("cp.async.commit_group;" ::: "memory")
#define CP_WAIT0()  asm volatile("cp.async.wait_group 0;" ::: "memory")

#define LDSM_X4(r0, r1, r2, r3, addr) \
    asm volatile("ldmatrix.sync.aligned.m8n8.x4.shared.b16 {%0,%1,%2,%3}, [%4];" \
        : "=r"(r0), "=r"(r1), "=r"(r2), "=r"(r3) : "r"(addr))
#define LDSM_X4T(r0, r1, r2, r3, addr) \
    asm volatile("ldmatrix.sync.aligned.m8n8.x4.trans.shared.b16 {%0,%1,%2,%3}, [%4];" \
        : "=r"(r0), "=r"(r1), "=r"(r2), "=r"(r3) : "r"(addr))

// m16n8k16 bf16 MMA (compute_80 baseline feature)
__device__ __forceinline__ void mma_bf16(float* d,
                                         uint32_t a0, uint32_t a1, uint32_t a2, uint32_t a3,
                                         uint32_t b0, uint32_t b1) {
    asm volatile(
        "mma.sync.aligned.m16n8k16.row.col.f32.bf16.bf16.f32 "
        "{%0,%1,%2,%3}, {%4,%5,%6,%7}, {%8,%9}, {%0,%1,%2,%3};"
        : "+f"(d[0]), "+f"(d[1]), "+f"(d[2]), "+f"(d[3])
        : "r"(a0), "r"(a1), "r"(a2), "r"(a3), "r"(b0), "r"(b1));
}

// ---------------- helpers ----------------
__device__ __forceinline__ float blockReduceSum128(float v, float* sred) {
    #pragma unroll
    for (int o = 16; o > 0; o >>= 1) v += __shfl_xor_sync(0xffffffffu, v, o);
    int w = threadIdx.x >> 5;
    if ((threadIdx.x & 31) == 0) sred[w] = v;
    __syncthreads();
    float r = sred[0] + sred[1] + sred[2] + sred[3];
    __syncthreads();
    return r;
}

// ---------------- K0: weight prep: hw = proj(expmap0(W,c),c) ----------------
__global__ __launch_bounds__(128) void k_prep(
    const float* __restrict__ lw, const float* __restrict__ lb,
    const float* __restrict__ aw, const float* __restrict__ ab,
    const float* __restrict__ cp)
{
    __shared__ float sred[4];
    const float c    = cp[0];
    const float sc   = sqrtf(c);
    const float maxn = (1.0f - 4e-3f) / sc;
    const int b = blockIdx.x, t = threadIdx.x;

    if (b < DOUT) {                       // hw1 rows (len 512) -> bf16 transposed [k][n]
        const float* u = lw + b * DIN;
        float ss = 0.f;
        #pragma unroll
        for (int i = t; i < DIN; i += 128) { float v = u[i]; ss += v * v; }
        ss = blockReduceSum128(ss, sred);
        float un = fmaxf(sqrtf(ss), 1e-15f);
        float f  = tanhf(sc * un) / (sc * un);
        float vn = fmaxf(sqrtf(f * f * ss), 1e-15f);
        float coef = f * (vn > maxn ? maxn / vn : 1.0f);
        for (int i = t; i < DIN; i += 128)
            g_hw1b[(size_t)i * DOUT + b] = __float2bfloat16(coef * u[i]);
    } else if (b < 2 * DOUT) {            // hw2 rows (len 128)
        int r = b - DOUT;
        const float* u = aw + r * DOUT;
        float x = u[t];
        float ss = blockReduceSum128(x * x, sred);
        float un = fmaxf(sqrtf(ss), 1e-15f);
        float f  = tanhf(sc * un) / (sc * un);
        float vn = fmaxf(sqrtf(f * f * ss), 1e-15f);
        float coef = f * (vn > maxn ? maxn / vn : 1.0f);
        g_hw2[r * DOUT + t] = coef * x;
    } else {                              // hb + bias sumsq scalars
        float x = lb[t];
        float ss = blockReduceSum128(x * x, sred);
        float un = fmaxf(sqrtf(ss), 1e-15f);
        float f  = tanhf(sc * un) / (sc * un);
        float vn = fmaxf(sqrtf(f * f * ss), 1e-15f);
        float coef = f * (vn > maxn ? maxn / vn : 1.0f);
        g_hb[t] = coef * x;
        if (t == 0) g_hb2s = coef * coef * ss;
        float y = ab[t];
        float s2 = blockReduceSum128(y * y, sred);
        if (t == 0) g_b2s = s2;
    }
}

// ============ shared bf16-MMA tile constants (K1, K3) ============
// CTA: M=64 x N=128, K chunked by 64, double-buffered dynamic smem.
// A smem [m=64][k=64] bf16, row stride 144 B -> ldmatrix conflict-free.
// B smem [k=64][n=128] bf16, row stride 272 B -> ldmatrix.trans conflict-free.
#define KC      64
#define ASTR_B  144
#define BSTR_B  272
#define A_BYTES (64 * ASTR_B)   // 9216
#define B_BYTES (KC * BSTR_B)   // 17408
#define DYN_SMEM (2 * (A_BYTES + B_BYTES))  // 53248

// ---------------- K1: h = hyp_linear(x,...) bf16 mma.sync ----------------
__global__ __launch_bounds__(256) void k_lin_mma(
    const float* __restrict__ x, const float* __restrict__ cp)
{
    extern __shared__ __align__(16) char dsm[];
    char* Ab0 = dsm;
    char* Bb0 = dsm + 2 * A_BYTES;
    __shared__ float bv[128];
    __shared__ float arow[64];
    __shared__ float sredS[64][2][3];

    const int t = threadIdx.x;
    const int w = t >> 5, l = t & 31;
    const int mb = (w & 3) * 16;
    const int nhalf = w >> 2;
    const int rowbase = blockIdx.x * 64;
    const float c  = cp[0];
    const float sc = sqrtf(c);

    if (t < 128) bv[t] = g_hb[t];

    const int arI = t >> 2, aq = t & 3;   // A loader: 4 threads/row, 16 floats each
    const float4* ap = (const float4*)(x + (size_t)(rowbase + arI) * DIN);
    const int bkr = t >> 2, bq = t & 3;   // B loader: 4 threads/k-row, 64 B each

    const uint32_t abase = smem_u32(Ab0);
    const uint32_t bbase = smem_u32(Bb0);

    float acc[8][4];
    #pragma unroll
    for (int i = 0; i < 8; i++)
        #pragma unroll
        for (int j = 0; j < 4; j++) acc[i][j] = 0.f;

    float asq = 0.f;
    float4 la[4];

    const int NCH = DIN / KC;  // 8

    // prologue: chunk 0
    #pragma unroll
    for (int i = 0; i < 4; i++) la[i] = ap[aq * 4 + i];
    #pragma unroll
    for (int i = 0; i < 2; i++) {
        float4 v0 = la[2 * i], v1 = la[2 * i + 1];
        asq += v0.x*v0.x + v0.y*v0.y + v0.z*v0.z + v0.w*v0.w
             + v1.x*v1.x + v1.y*v1.y + v1.z*v1.z + v1.w*v1.w;
        uint4 u = make_uint4(pack_bf16(v0.x, v0.y), pack_bf16(v0.z, v0.w),
                             pack_bf16(v1.x, v1.y), pack_bf16(v1.z, v1.w));
        *(uint4*)&Ab0[arI * ASTR_B + aq * 32 + i * 16] = u;
    }
    #pragma unroll
    for (int i = 0; i < 4; i++)
        cp_async16(bbase + (uint32_t)(bkr * BSTR_B + bq * 64 + i * 16),
                   (const char*)g_hw1b + ((size_t)bkr * DOUT + bq * 32 + i * 8) * 2);
    CP_COMMIT();
    CP_WAIT0();
    __syncthreads();

    for (int ck = 0; ck < NCH; ++ck) {
        const int cur = ck & 1, nxt = cur ^ 1;
        const bool more = (ck + 1 < NCH);
        if (more) {
            #pragma unroll
            for (int i = 0; i < 4; i++) la[i] = ap[(ck + 1) * 16 + aq * 4 + i];
            #pragma unroll
            for (int i = 0; i < 4; i++)
                cp_async16(bbase + (uint32_t)(nxt * B_BYTES + bkr * BSTR_B + bq * 64 + i * 16),
                           (const char*)g_hw1b + ((size_t)((ck + 1) * KC + bkr) * DOUT + bq * 32 + i * 8) * 2);
            CP_COMMIT();
        }
        {
            const uint32_t aT = abase + (uint32_t)cur * A_BYTES;
            const uint32_t bT = bbase + (uint32_t)cur * B_BYTES;
            #pragma unroll
            for (int ks = 0; ks < 4; ks++) {
                uint32_t a0, a1, a2, a3;
                uint32_t aaddr = aT + (uint32_t)((mb + (l & 15)) * ASTR_B + ks * 32 + (l >> 4) * 16);
                LDSM_X4(a0, a1, a2, a3, aaddr);
                #pragma unroll
                for (int p = 0; p < 4; p++) {
                    uint32_t b0, b1, b2, b3;
                    uint32_t baddr = bT + (uint32_t)((ks * 16 + (l & 15)) * BSTR_B
                                   + nhalf * 128 + (2 * p + (l >> 4)) * 16);
                    LDSM_X4T(b0, b1, b2, b3, baddr);
                    mma_bf16(acc[2 * p],     a0, a1, a2, a3, b0, b1);
                    mma_bf16(acc[2 * p + 1], a0, a1, a2, a3, b2, b3);
                }
            }
        }
        if (more) {
            #pragma unroll
            for (int i = 0; i < 2; i++) {
                float4 v0 = la[2 * i], v1 = la[2 * i + 1];
                asq += v0.x*v0.x + v0.y*v0.y + v0.z*v0.z + v0.w*v0.w
                     + v1.x*v1.x + v1.y*v1.y + v1.z*v1.z + v1.w*v1.w;
                uint4 u = make_uint4(pack_bf16(v0.x, v0.y), pack_bf16(v0.z, v0.w),
                                     pack_bf16(v1.x, v1.y), pack_bf16(v1.z, v1.w));
                *(uint4*)&Ab0[nxt * A_BYTES + arI * ASTR_B + aq * 32 + i * 16] = u;
            }
            CP_WAIT0();
        }
        __syncthreads();
    }

    // x row sumsq: combine 4 loader threads per row
    asq += __shfl_xor_sync(0xffffffffu, asq, 1);
    asq += __shfl_xor_sync(0xffffffffu, asq, 2);
    if ((t & 3) == 0) arow[arI] = asq;
    __syncthreads();

    // fragment-domain hyp_linear epilogue
    float S1[2] = {0.f, 0.f}, S2[2] = {0.f, 0.f}, S3[2] = {0.f, 0.f};
    #pragma unroll
    for (int nt = 0; nt < 8; nt++) {
        const int col = nhalf * 64 + nt * 8 + 2 * (l & 3);
        const float b0 = bv[col], b1 = bv[col + 1];
        float c0 = acc[nt][0], c1 = acc[nt][1], c2 = acc[nt][2], c3 = acc[nt][3];
        S1[0] += c0*c0 + c1*c1;  S2[0] += fabsf(c0) + fabsf(c1);  S3[0] += c0*b0 + c1*b1;
        S1[1] += c2*c2 + c3*c3;  S2[1] += fabsf(c2) + fabsf(c3);  S3[1] += c2*b0 + c3*b1;
    }
    #pragma unroll
    for (int r = 0; r < 2; r++) {
        S1[r] += __shfl_xor_sync(0xffffffffu, S1[r], 1);
        S1[r] += __shfl_xor_sync(0xffffffffu, S1[r], 2);
        S2[r] += __shfl_xor_sync(0xffffffffu, S2[r], 1);
        S2[r] += __shfl_xor_sync(0xffffffffu, S2[r], 2);
        S3[r] += __shfl_xor_sync(0xffffffffu, S3[r], 1);
        S3[r] += __shfl_xor_sync(0xffffffffu, S3[r], 2);
    }
    if ((l & 3) == 0) {
        const int r0 = mb + (l >> 2);
        sredS[r0][nhalf][0] = S1[0]; sredS[r0][nhalf][1] = S2[0]; sredS[r0][nhalf][2] = S3[0];
        sredS[r0 + 8][nhalf][0] = S1[1]; sredS[r0 + 8][nhalf][1] = S2[1]; sredS[r0 + 8][nhalf][2] = S3[1];
    }
    __syncthreads();

    float Pr[2], Qr[2];
    const float y2 = g_hb2s;
    const float maxn = (1.0f - 4e-3f) / sc;
    #pragma unroll
    for (int r = 0; r < 2; r++) {
        const int rl = mb + (l >> 2) + r * 8;
        float S1t = sredS[rl][0][0] + sredS[rl][1][0];
        float S2t = sredS[rl][0][1] + sredS[rl][1][1];
        float S3t = sredS[rl][0][2] + sredS[rl][1][2];
        float xn  = fmaxf(sqrtf(arow[rl]), 1e-15f);
        float mxn = fmaxf(sqrtf(S1t), 1e-15f);
        float at  = atanhf(fminf(sc * xn, 1.0f - 1e-7f));
        float s   = tanhf(mxn / xn * at) / (mxn * sc);
        if (S2t == 0.f) s = 0.f;
        float rn = fmaxf(sqrtf(s * s * S1t), 1e-15f);
        if (rn > maxn) s *= maxn / rn;          // proj before mobius_add
        float x2 = s * s * S1t;
        float xy = s * S3t;
        float Aa = 1.0f + 2.0f * c * xy + c * y2;
        float Bb2 = 1.0f - c * x2;
        float den = fmaxf(1.0f + 2.0f * c * xy + c * c * x2 * y2, 1e-15f);
        float P = Aa * s / den, Q = Bb2 / den;
        float h2 = P * P * S1t + 2.0f * P * Q * S3t + Q * Q * y2;
        float hn = fmaxf(sqrtf(h2), 1e-15f);
        if (hn > maxn) { float g = maxn / hn; P *= g; Q *= g; hn = maxn; }
        Pr[r] = P; Qr[r] = Q;
        if (((l & 3) == 0) && nhalf == 0) g_hn[rowbase + rl] = hn;
    }

    const int g0 = rowbase + mb + (l >> 2);
    #pragma unroll
    for (int nt = 0; nt < 8; nt++) {
        const int col = nhalf * 64 + nt * 8 + 2 * (l & 3);
        *(float2*)&g_h[(size_t)g0 * DOUT + col] =
            make_float2(Pr[0] * acc[nt][0] + Qr[0] * bv[col],
                        Pr[0] * acc[nt][1] + Qr[0] * bv[col + 1]);
        *(float2*)&g_h[(size_t)(g0 + 8) * DOUT + col] =
            make_float2(Pr[1] * acc[nt][2] + Qr[1] * bv[col],
                        Pr[1] * acc[nt][3] + Qr[1] * bv[col + 1]);
    }
}

// ============ FFMA GEMM tile config (K2) ============
#define BK  32
#define BMP 68
#define BN  128

// ---------------- K2: support = mobius_matvec(hw2, h) fused GEMM -> bf16 ----------------
__global__ __launch_bounds__(128) void k_sup_gemm(const float* __restrict__ cp) {
    __shared__ __align__(16) float pool[BK * BMP + BK * BN];
    __shared__ float par[64];
    float* As = pool;
    float* Bs = pool + BK * BMP;

    const int t = threadIdx.x;
    const int rowbase = blockIdx.x * 64;
    const float c  = cp[0];
    const float sc = sqrtf(c);

    const int tr = t >> 4, tc = t & 15;
    const int ar = t >> 3, ac = (t & 7) * 4;

    float acc[8][8];
    #pragma unroll
    for (int i = 0; i < 8; i++)
        #pragma unroll
        for (int j = 0; j < 8; j++) acc[i][j] = 0.f;

    float4 la[4], lb8[8];
    #pragma unroll
    for (int p = 0; p < 4; p++)
        la[p] = *(const float4*)&g_h[(size_t)(rowbase + p * 16 + ar) * DOUT + ac];
    #pragma unroll
    for (int f = 0; f < 8; f++)
        lb8[f] = *(const float4*)&g_hw2[t * DOUT + f * 4];

    const int ITERS = DOUT / BK;  // 4
    for (int it = 0; it < ITERS; ++it) {
        __syncthreads();
        #pragma unroll
        for (int p = 0; p < 4; p++) {
            float4 v = la[p]; int r = p * 16 + ar;
            As[(ac + 0) * BMP + r] = v.x; As[(ac + 1) * BMP + r] = v.y;
            As[(ac + 2) * BMP + r] = v.z; As[(ac + 3) * BMP + r] = v.w;
        }
        #pragma unroll
        for (int f = 0; f < 8; f++) {
            float4 v = lb8[f];
            Bs[(f * 4 + 0) * BN + t] = v.x; Bs[(f * 4 + 1) * BN + t] = v.y;
            Bs[(f * 4 + 2) * BN + t] = v.z; Bs[(f * 4 + 3) * BN + t] = v.w;
        }
        __syncthreads();
        if (it + 1 < ITERS) {
            int kt = (it + 1) * BK;
            #pragma unroll
            for (int p = 0; p < 4; p++)
                la[p] = *(const float4*)&g_h[(size_t)(rowbase + p * 16 + ar) * DOUT + kt + ac];
            #pragma unroll
            for (int f = 0; f < 8; f++)
                lb8[f] = *(const float4*)&g_hw2[t * DOUT + kt + f * 4];
        }
        #pragma unroll
        for (int kk = 0; kk < BK; kk++) {
            float4 a0 = *(const float4*)&As[kk * BMP + tr * 8];
            float4 a1 = *(const float4*)&As[kk * BMP + tr * 8 + 4];
            float4 b0 = *(const float4*)&Bs[kk * BN + tc * 4];
            float4 b1 = *(const float4*)&Bs[kk * BN + tc * 4 + 64];
            float av[8] = {a0.x,a0.y,a0.z,a0.w,a1.x,a1.y,a1.z,a1.w};
            float bv[8] = {b0.x,b0.y,b0.z,b0.w,b1.x,b1.y,b1.z,b1.w};
            #pragma unroll
            for (int i = 0; i < 8; i++)
                #pragma unroll
                for (int j = 0; j < 8; j++) acc[i][j] += av[i] * bv[j];
        }
    }
    __syncthreads();

    float* red = pool;  // [64][16][2]
    #pragma unroll
    for (int i = 0; i < 8; i++) {
        int r = tr * 8 + i;
        float p1 = 0.f, p2 = 0.f;
        #pragma unroll
        for (int j = 0; j < 8; j++) { float v = acc[i][j]; p1 += v * v; p2 += fabsf(v); }
        red[(r * 16 + tc) * 2 + 0] = p1;
        red[(r * 16 + tc) * 2 + 1] = p2;
    }
    __syncthreads();
    if (t < 64) {
        float S1 = 0.f, S2 = 0.f;
        #pragma unroll
        for (int q = 0; q < 16; q++) {
            S1 += red[(t * 16 + q) * 2 + 0];
            S2 += red[(t * 16 + q) * 2 + 1];
        }
        float hn  = g_hn[rowbase + t];
        float mxn = fmaxf(sqrtf(S1), 1e-15f);
        float at  = atanhf(fminf(sc * hn, 1.0f - 1e-7f));
        float s   = tanhf(mxn / hn * at) / (mxn * sc);
        if (S2 == 0.f) s = 0.f;
        par[t] = s;
    }
    __syncthreads();
    #pragma unroll
    for (int i = 0; i < 8; i++) {
        int r = tr * 8 + i;
        float s = par[r];
        uint32_t u0 = pack_bf16(s * acc[i][0], s * acc[i][1]);
        uint32_t u1 = pack_bf16(s * acc[i][2], s * acc[i][3]);
        uint32_t u2 = pack_bf16(s * acc[i][4], s * acc[i][5]);
        uint32_t u3 = pack_bf16(s * acc[i][6], s * acc[i][7]);
        *(uint2*)&g_supb[(size_t)(rowbase + r) * DOUT + tc * 4]      = make_uint2(u0, u1);
        *(uint2*)&g_supb[(size_t)(rowbase + r) * DOUT + 64 + tc * 4] = make_uint2(u2, u3);
    }
}

// ---------------- K3: bf16 mma.sync adj@sup + fused hyperbolic epilogue ----------------
// 128 CTAs x 256 threads (8 warps). CTA: M=64 x N=128, K=8192 chunked by KC=64.
__global__ __launch_bounds__(256) void k_agg_mma(
    const float* __restrict__ adj, const float* __restrict__ bias,
    const float* __restrict__ cp, float* __restrict__ out)
{
    extern __shared__ __align__(16) char dsm[];
    char* Ab0 = dsm;
    char* Bb0 = dsm + 2 * A_BYTES;
    __shared__ float bv[128];
    __shared__ float arow[64];
    __shared__ float sredS[64][2][3];
    __shared__ float sredQ[64][2];

    const int t = threadIdx.x;
    const int w = t >> 5, l = t & 31;
    const int mb = (w & 3) * 16;
    const int nhalf = w >> 2;
    const int rowbase = blockIdx.x * 64;
    const float c  = cp[0];
    const float sc = sqrtf(c);

    if (t < 128) bv[t] = bias[t];

    const int arI = t >> 2, aq = t & 3;
    const float4* ap = (const float4*)(adj + (size_t)(rowbase + arI) * NR);
    const int bkr = t >> 2, bq = t & 3;

    const uint32_t abase = smem_u32(Ab0);
    const uint32_t bbase = smem_u32(Bb0);

    float acc[8][4];
    #pragma unroll
    for (int i = 0; i < 8; i++)
        #pragma unroll
        for (int j = 0; j < 4; j++) acc[i][j] = 0.f;

    float asq = 0.f;
    float4 la[4];

    const int NCH = NR / KC;  // 128

    // prologue: chunk 0
    #pragma unroll
    for (int i = 0; i < 4; i++) la[i] = ap[aq * 4 + i];
    #pragma unroll
    for (int i = 0; i < 2; i++) {
        float4 v0 = la[2 * i], v1 = la[2 * i + 1];
        asq += v0.x*v0.x + v0.y*v0.y + v0.z*v0.z + v0.w*v0.w
             + v1.x*v1.x + v1.y*v1.y + v1.z*v1.z + v1.w*v1.w;
        uint4 u = make_uint4(pack_bf16(v0.x, v0.y), pack_bf16(v0.z, v0.w),
                             pack_bf16(v1.x, v1.y), pack_bf16(v1.z, v1.w));
        *(uint4*)&Ab0[arI * ASTR_B + aq * 32 + i * 16] = u;
    }
    #pragma unroll
    for (int i = 0; i < 4; i++)
        cp_async16(bbase + (uint32_t)(bkr * BSTR_B + bq * 64 + i * 16),
                   (const char*)g_supb + ((size_t)bkr * DOUT + bq * 32 + i * 8) * 2);
    CP_COMMIT();
    CP_WAIT0();
    __syncthreads();

    for (int ck = 0; ck < NCH; ++ck) {
        const int cur = ck & 1, nxt = cur ^ 1;
        const bool more = (ck + 1 < NCH);
        if (more) {
            #pragma unroll
            for (int i = 0; i < 4; i++) la[i] = ap[(ck + 1) * 16 + aq * 4 + i];
            #pragma unroll
            for (int i = 0; i < 4; i++)
                cp_async16(bbase + (uint32_t)(nxt * B_BYTES + bkr * BSTR_B + bq * 64 + i * 16),
                           (const char*)g_supb + ((size_t)((ck + 1) * KC + bkr) * DOUT + bq * 32 + i * 8) * 2);
            CP_COMMIT();
        }
        {
            const uint32_t aT = abase + (uint32_t)cur * A_BYTES;
            const uint32_t bT = bbase + (uint32_t)cur * B_BYTES;
            #pragma unroll
            for (int ks = 0; ks < 4; ks++) {
                uint32_t a0, a1, a2, a3;
                uint32_t aaddr = aT + (uint32_t)((mb + (l & 15)) * ASTR_B + ks * 32 + (l >> 4) * 16);
                LDSM_X4(a0, a1, a2, a3, aaddr);
                #pragma unroll
                for (int p = 0; p < 4; p++) {
                    uint32_t b0, b1, b2, b3;
                    uint32_t baddr = bT + (uint32_t)((ks * 16 + (l & 15)) * BSTR_B
                                   + nhalf * 128 + (2 * p + (l >> 4)) * 16);
                    LDSM_X4T(b0, b1, b2, b3, baddr);
                    mma_bf16(acc[2 * p],     a0, a1, a2, a3, b0, b1);
                    mma_bf16(acc[2 * p + 1], a0, a1, a2, a3, b2, b3);
                }
            }
        }
        if (more) {
            #pragma unroll
            for (int i = 0; i < 2; i++) {
                float4 v0 = la[2 * i], v1 = la[2 * i + 1];
                asq += v0.x*v0.x + v0.y*v0.y + v0.z*v0.z + v0.w*v0.w
                     + v1.x*v1.x + v1.y*v1.y + v1.z*v1.z + v1.w*v1.w;
                uint4 u = make_uint4(pack_bf16(v0.x, v0.y), pack_bf16(v0.z, v0.w),
                                     pack_bf16(v1.x, v1.y), pack_bf16(v1.z, v1.w));
                *(uint4*)&Ab0[nxt * A_BYTES + arI * ASTR_B + aq * 32 + i * 16] = u;
            }
            CP_WAIT0();
        }
        __syncthreads();
    }

    // adj row sumsq: combine 4 loader threads per row
    asq += __shfl_xor_sync(0xffffffffu, asq, 1);
    asq += __shfl_xor_sync(0xffffffffu, asq, 2);
    if ((t & 3) == 0) arow[arI] = asq;
    __syncthreads();

    // fragment-domain hyperbolic epilogue
    float S1[2] = {0.f, 0.f}, S2[2] = {0.f, 0.f}, S3[2] = {0.f, 0.f};
    #pragma unroll
    for (int nt = 0; nt < 8; nt++) {
        const int col = nhalf * 64 + nt * 8 + 2 * (l & 3);
        const float b0 = bv[col], b1 = bv[col + 1];
        float c0 = acc[nt][0], c1 = acc[nt][1], c2 = acc[nt][2], c3 = acc[nt][3];
        S1[0] += c0*c0 + c1*c1;  S2[0] += fabsf(c0) + fabsf(c1);  S3[0] += c0*b0 + c1*b1;
        S1[1] += c2*c2 + c3*c3;  S2[1] += fabsf(c2) + fabsf(c3);  S3[1] += c2*b0 + c3*b1;
    }
    #pragma unroll
    for (int r = 0; r < 2; r++) {
        S1[r] += __shfl_xor_sync(0xffffffffu, S1[r], 1);
        S1[r] += __shfl_xor_sync(0xffffffffu, S1[r], 2);
        S2[r] += __shfl_xor_sync(0xffffffffu, S2[r], 1);
        S2[r] += __shfl_xor_sync(0xffffffffu, S2[r], 2);
        S3[r] += __shfl_xor_sync(0xffffffffu, S3[r], 1);
        S3[r] += __shfl_xor_sync(0xffffffffu, S3[r], 2);
    }
    if ((l & 3) == 0) {
        const int r0 = mb + (l >> 2);
        sredS[r0][nhalf][0] = S1[0]; sredS[r0][nhalf][1] = S2[0]; sredS[r0][nhalf][2] = S3[0];
        sredS[r0 + 8][nhalf][0] = S1[1]; sredS[r0 + 8][nhalf][1] = S2[1]; sredS[r0 + 8][nhalf][2] = S3[1];
    }
    __syncthreads();

    float Pr[2], Qr[2], Lr[2];
    const float y2 = g_b2s;
    const float maxn = (1.0f - 4e-3f) / sc;
    #pragma unroll
    for (int r = 0; r < 2; r++) {
        const int rl = mb + (l >> 2) + r * 8;
        float S1t = sredS[rl][0][0] + sredS[rl][1][0];
        float S2t = sredS[rl][0][1] + sredS[rl][1][1];
        float S3t = sredS[rl][0][2] + sredS[rl][1][2];
        float an  = fmaxf(sqrtf(arow[rl]), 1e-15f);
        float mxn = fmaxf(sqrtf(S1t), 1e-15f);
        float at  = atanhf(fminf(sc * an, 1.0f - 1e-7f));
        float s   = tanhf(mxn / an * at) / (mxn * sc);
        if (S2t == 0.f) s = 0.f;
        float x2 = s * s * S1t;
        float xy = s * S3t;
        float Aa = 1.0f + 2.0f * c * xy + c * y2;
        float Bb2 = 1.0f - c * x2;
        float den = fmaxf(1.0f + 2.0f * c * xy + c * c * x2 * y2, 1e-15f);
        float P = Aa * s / den, Q = Bb2 / den;
        float g2 = P * P * S1t + 2.0f * P * Q * S3t + Q * Q * y2;
        float gn = fmaxf(sqrtf(g2), 1e-15f);
        if (gn > maxn) { float g = maxn / gn; P *= g; Q *= g; gn = maxn; }
        Pr[r] = P; Qr[r] = Q;
        Lr[r] = atanhf(fminf(sc * gn, 1.0f - 1e-7f)) / (gn * sc);
    }

    float q2[2] = {0.f, 0.f};
    #pragma unroll
    for (int nt = 0; nt < 8; nt++) {
        const int col = nhalf * 64 + nt * 8 + 2 * (l & 3);
        const float b0 = bv[col], b1 = bv[col + 1];
        float v0 = Lr[0] * (Pr[0] * acc[nt][0] + Qr[0] * b0);
        float v1 = Lr[0] * (Pr[0] * acc[nt][1] + Qr[0] * b1);
        float v2 = Lr[1] * (Pr[1] * acc[nt][2] + Qr[1] * b0);
        float v3 = Lr[1] * (Pr[1] * acc[nt][3] + Qr[1] * b1);
        v0 = (v0 >= 0.f) ? v0 : 0.01f * v0;
        v1 = (v1 >= 0.f) ? v1 : 0.01f * v1;
        v2 = (v2 >= 0.f) ? v2 : 0.01f * v2;
        v3 = (v3 >= 0.f) ? v3 : 0.01f * v3;
        acc[nt][0] = v0; acc[nt][1] = v1; acc[nt][2] = v2; acc[nt][3] = v3;
        q2[0] += v0*v0 + v1*v1;
        q2[1] += v2*v2 + v3*v3;
    }
    #pragma unroll
    for (int r = 0; r < 2; r++) {
        q2[r] += __shfl_xor_sync(0xffffffffu, q2[r], 1);
        q2[r] += __shfl_xor_sync(0xffffffffu, q2[r], 2);
    }
    if ((l & 3) == 0) {
        const int r0 = mb + (l >> 2);
        sredQ[r0][nhalf] = q2[0];
        sredQ[r0 + 8][nhalf] = q2[1];
    }
    __syncthreads();

    float er[2];
    const float sc2 = sqrtf(1.0f - c);
    const float mn2 = (1.0f - 4e-3f) / sc2;
    #pragma unroll
    for (int r = 0; r < 2; r++) {
        const int rl = mb + (l >> 2) + r * 8;
        float q2t = sredQ[rl][0] + sredQ[rl][1];
        float un = fmaxf(sqrtf(q2t), 1e-15f);
        float e  = tanhf(sc * un) / (sc * un);      // expmap0 with curvature c
        float vn = fmaxf(sqrtf(e * e * q2t), 1e-15f);
        if (vn > mn2) e *= mn2 / vn;                // proj with curvature 1-c
        er[r] = e;
    }

    const int g0 = rowbase + mb + (l >> 2);
    #pragma unroll
    for (int nt = 0; nt < 8; nt++) {
        const int col = nhalf * 64 + nt * 8 + 2 * (l & 3);
        *(float2*)&out[(size_t)g0 * DOUT + col] =
            make_float2(er[0] * acc[nt][0], er[0] * acc[nt][1]);
        *(float2*)&out[(size_t)(g0 + 8) * DOUT + col] =
            make_float2(er[1] * acc[nt][2], er[1] * acc[nt][3]);
    }
}

// ---------------- launch ----------------
extern "C" void kernel_launch(void* const* d_in, const int* in_sizes, int n_in,
                              void* d_out, int out_size)
{
    const float* x   = (const float*)d_in[0];
    const float* adj = (const float*)d_in[1];
    const float* cp  = (const float*)d_in[2];
    const float* lw  = (const float*)d_in[3];
    const float* lb  = (const float*)d_in[4];
    const float* aw  = (const float*)d_in[5];
    const float* ab  = (const float*)d_in[6];
    float* out = (float*)d_out;

    cudaFuncSetAttribute(k_lin_mma, cudaFuncAttributeMaxDynamicSharedMemorySize, DYN_SMEM);
    cudaFuncSetAttribute(k_agg_mma, cudaFuncAttributeMaxDynamicSharedMemorySize, DYN_SMEM);

    k_prep<<<2 * DOUT + 1, 128>>>(lw, lb, aw, ab, cp);
    k_lin_mma<<<NR / 64, 256, DYN_SMEM>>>(x, cp);
    k_sup_gemm<<<NR / 64, 128>>>(cp);
    k_agg_mma<<<NR / 64, 256, DYN_SMEM>>>(adj, ab, cp, out);
}